// round 9
// baseline (speedup 1.0000x reference)
#include <cuda_runtime.h>
#include <cuda_bf16.h>
#include <cstdint>

// Problem constants (fixed shapes)
#define Bn 32
#define Sn 1024
#define Hn 1024
#define Wn 128
#define Kn 6
#define NH 16
#define HD 64
#define MROWS (Bn * Wn * Kn)   // 24576
#define NCOLS (2 * Hn)         // 2048

// Scratch for qk projection output: 24576 x 2048 f32 = ~201 MB
__device__ float g_qk[(size_t)MROWS * NCOLS];

__device__ __forceinline__ uint32_t smem_u32(const void* p) {
    uint32_t a;
    asm("{ .reg .u64 t; cvta.to.shared.u64 t, %1; cvt.u32.u64 %0, t; }" : "=r"(a) : "l"(p));
    return a;
}
__device__ __forceinline__ void mma_tf32(float& c0, float& c1, float& c2, float& c3,
                                         uint32_t a0, uint32_t a1, uint32_t a2, uint32_t a3,
                                         uint32_t b0, uint32_t b1)
{
    asm volatile(
        "mma.sync.aligned.m16n8k8.row.col.f32.tf32.tf32.f32 "
        "{%0,%1,%2,%3},{%4,%5,%6,%7},{%8,%9},{%0,%1,%2,%3};"
        : "+f"(c0), "+f"(c1), "+f"(c2), "+f"(c3)
        : "r"(a0), "r"(a1), "r"(a2), "r"(a3), "r"(b0), "r"(b1));
}
__device__ __forceinline__ void ldsm4(uint32_t& r0, uint32_t& r1, uint32_t& r2, uint32_t& r3,
                                      uint32_t addr)
{
    asm volatile("ldmatrix.sync.aligned.m8n8.x4.shared.b16 {%0,%1,%2,%3}, [%4];"
                 : "=r"(r0), "=r"(r1), "=r"(r2), "=r"(r3) : "r"(addr));
}
__device__ __forceinline__ void cpasync16(uint32_t dst, const float* src, uint32_t sz) {
    asm volatile("cp.async.cg.shared.global [%0], [%1], 16, %2;"
                 :: "r"(dst), "l"(src), "r"(sz) : "memory");
}
#define CP_COMMIT() asm volatile("cp.async.commit_group;" ::: "memory")
#define CP_WAIT(n)  asm volatile("cp.async.wait_group %0;" :: "n"(n) : "memory")
#define SW128(o) ((o) ^ (((o) >> 3) & 0x70))

// ---------------------------------------------------------------------------
// Kernel A: gathered TF32 tensor-core GEMM, cp.async in + ldmatrix out of smem.
//   qk[r][c] = sum_h x[r][h] * Wt[c][h] + bias[c],  x[r] = mask ? TE[b,idx[r]] : 0
// Tile 128x128, 6 stages of BK=16 processed/prefetched 2 per barrier
// (32 sync points), 256 threads (8 warps 4x2), warp tile 32x64.
// SMEM: [0:1024) srcOff, [1024:1536) bias, [2048 + s*16KB) stages (A 8KB | B 8KB)
// A/B stage layout: 128 rows x 16 floats (64B rows), SW128-swizzled 16B chunks.
// ---------------------------------------------------------------------------
#define STAGE_BYTES 16384
#define NSTAGE 6
#define GEMM_SMEM (2048 + NSTAGE * STAGE_BYTES)

__global__ __launch_bounds__(256, 2) void gemm_qk_cp(
    const float* __restrict__ TE,
    const float* __restrict__ Wt,
    const float* __restrict__ bias,
    const int* __restrict__ idx)
{
    extern __shared__ unsigned char sm[];
    long long* srcOff = (long long*)sm;
    float* biasSm = (float*)(sm + 1024);
    const uint32_t smBase = smem_u32(sm);

    const int tid = threadIdx.x;
    const int rowBase = blockIdx.y * 128;
    const int colBase = blockIdx.x * 128;

    if (tid < 128) {
        int r = rowBase + tid;
        int b = r / (Wn * Kn);
        int kk = r % Kn;                 // (Wn*Kn) % Kn == 0
        int iv = idx[r];
        bool m = (kk == 0) || (iv != 0);
        srcOff[tid] = m ? ((long long)(b * Sn + iv) * Hn) : -1LL;
        biasSm[tid] = bias[colBase + tid];
    }
    __syncthreads();

    // ---- loader mapping: thread t -> row t>>1, k-half t&1 (8 floats) ----
    const int lrow = tid >> 1;
    const int lhalf = tid & 1;
    const long long aOff = srcOff[lrow];
    const float* aSrc = TE + (aOff >= 0 ? aOff : 0) + lhalf * 8;
    const uint32_t aSz = (aOff >= 0) ? 16u : 0u;
    const float* bSrc = Wt + (size_t)(colBase + lrow) * Hn + lhalf * 8;

    const uint32_t dOff = (uint32_t)(lrow * 64 + lhalf * 32);
    const uint32_t aD0 = smBase + 2048 + SW128(dOff);
    const uint32_t aD1 = smBase + 2048 + SW128(dOff + 16);
    const uint32_t bD0 = aD0 + 8192;
    const uint32_t bD1 = aD1 + 8192;

    // ---- compute mapping ----
    const int wid = tid >> 5, lane = tid & 31;
    const int wr = wid >> 1, wc = wid & 1;            // 4 x 2 warp grid
    const int g4 = lane >> 2, t4 = lane & 3;

    // ldmatrix source addresses (stage-0 bases; add stage offset, XOR ks*32)
    uint32_t aLd[2];
    {
        const int rowsel = (lane & 7) + ((lane >> 3) & 1) * 8;
        const uint32_t colHalf = (uint32_t)((lane >> 4) & 1) * 16u;
#pragma unroll
        for (int mi = 0; mi < 2; mi++) {
            uint32_t o = (uint32_t)((wr * 32 + mi * 16 + rowsel) * 64) + colHalf;
            aLd[mi] = smBase + 2048 + SW128(o);
        }
    }
    uint32_t bLd[4];
    {
        const int rowsel = (lane & 7) + ((lane >> 4) & 1) * 8;
        const uint32_t colHalf = (uint32_t)((lane >> 3) & 1) * 16u;
#pragma unroll
        for (int p = 0; p < 4; p++) {
            uint32_t o = (uint32_t)((wc * 64 + p * 16 + rowsel) * 64) + colHalf;
            bLd[p] = smBase + 2048 + 8192 + SW128(o);
        }
    }

    float acc[2][8][4];
#pragma unroll
    for (int mi = 0; mi < 2; mi++)
#pragma unroll
        for (int ni = 0; ni < 8; ni++)
#pragma unroll
            for (int q = 0; q < 4; q++) acc[mi][ni][q] = 0.f;

    // ---- prologue: prefetch groups 0,1 (stages 0..3) ----
#pragma unroll
    for (int gr = 0; gr < 2; gr++) {
#pragma unroll
        for (int h = 0; h < 2; h++) {
            const int s = gr * 2 + h;
            const uint32_t sb = (uint32_t)(s * STAGE_BYTES);
            const int k0 = s * 16;
            cpasync16(aD0 + sb, aSrc + k0, aSz);
            cpasync16(aD1 + sb, aSrc + k0 + 4, aSz);
            cpasync16(bD0 + sb, bSrc + k0, 16u);
            cpasync16(bD1 + sb, bSrc + k0 + 4, 16u);
        }
        CP_COMMIT();
    }

    // ---- mainloop: 32 groups of 2 stages (BK=32 per barrier) ----
    for (int g = 0; g < 32; ++g) {
        CP_WAIT(1);
        __syncthreads();

        // prefetch group g+2 (stages 2g+4, 2g+5) over group g-1's buffers
        if (g + 2 < 32) {
#pragma unroll
            for (int h = 0; h < 2; h++) {
                const int s = 2 * (g + 2) + h;
                const uint32_t sb = (uint32_t)((s % NSTAGE) * STAGE_BYTES);
                const int k0 = s * 16;
                cpasync16(aD0 + sb, aSrc + k0, aSz);
                cpasync16(aD1 + sb, aSrc + k0 + 4, aSz);
                cpasync16(bD0 + sb, bSrc + k0, 16u);
                cpasync16(bD1 + sb, bSrc + k0 + 4, 16u);
            }
        }
        CP_COMMIT();

        // compute stages 2g, 2g+1
#pragma unroll
        for (int h = 0; h < 2; h++) {
            const uint32_t sb = (uint32_t)(((2 * g + h) % NSTAGE) * STAGE_BYTES);
#pragma unroll
            for (int ks = 0; ks < 2; ks++) {
                const uint32_t kx = (uint32_t)(ks * 32);
                uint32_t af[2][4];
#pragma unroll
                for (int mi = 0; mi < 2; mi++)
                    ldsm4(af[mi][0], af[mi][1], af[mi][2], af[mi][3],
                          (aLd[mi] + sb) ^ kx);

                uint32_t bf[4][4];   // [p]{b0(2p),b1(2p),b0(2p+1),b1(2p+1)}
#pragma unroll
                for (int p = 0; p < 4; p++)
                    ldsm4(bf[p][0], bf[p][1], bf[p][2], bf[p][3],
                          (bLd[p] + sb) ^ kx);

#pragma unroll
                for (int p = 0; p < 4; p++)
#pragma unroll
                    for (int hh = 0; hh < 2; hh++) {
                        const int ni = 2 * p + hh;
#pragma unroll
                        for (int mi = 0; mi < 2; mi++)
                            mma_tf32(acc[mi][ni][0], acc[mi][ni][1], acc[mi][ni][2], acc[mi][ni][3],
                                     af[mi][0], af[mi][1], af[mi][2], af[mi][3],
                                     bf[p][2 * hh], bf[p][2 * hh + 1]);
                    }
            }
        }
    }

    // ---- epilogue: add bias, store to g_qk ----
#pragma unroll
    for (int mi = 0; mi < 2; mi++) {
        int row0 = rowBase + wr * 32 + mi * 16 + g4;
#pragma unroll
        for (int ni = 0; ni < 8; ni++) {
            int cl = wc * 64 + ni * 8 + t4 * 2;
            float b0 = biasSm[cl], b1 = biasSm[cl + 1];
            float2 v0 = make_float2(acc[mi][ni][0] + b0, acc[mi][ni][1] + b1);
            float2 v1 = make_float2(acc[mi][ni][2] + b0, acc[mi][ni][3] + b1);
            *(float2*)&g_qk[(size_t)row0 * NCOLS + colBase + cl] = v0;
            *(float2*)&g_qk[(size_t)(row0 + 8) * NCOLS + colBase + cl] = v1;
        }
    }
}

// ---------------------------------------------------------------------------
// Kernel B: copy token_embeddings -> out, zeroing all masked subtoken rows.
// ---------------------------------------------------------------------------
__global__ __launch_bounds__(256) void copy_zero_kernel(
    const float* __restrict__ TE,
    const int* __restrict__ idx,
    float* __restrict__ out)
{
    size_t gid = (size_t)blockIdx.x * 256 + threadIdx.x;  // float4 index
    int row = (int)(gid >> 8);        // H/4 = 256 float4 per row
    int b = row >> 10;                // / S
    int s = row & 1023;
    int w = s >> 3;
    int kk = s & 7;
    bool zero = false;
    if (kk < Kn) {
        int iv = idx[(b * Wn + w) * Kn + kk];
        zero = (kk == 0) || (iv != 0);
    }
    float4 v;
    if (zero) {
        v = make_float4(0.f, 0.f, 0.f, 0.f);
    } else {
        v = ((const float4*)TE)[gid];
    }
    ((float4*)out)[gid] = v;
}

// ---------------------------------------------------------------------------
// Kernel C: per-window attention -> contrib -> unified, scatter to out.
// ---------------------------------------------------------------------------
struct SmemB {
    float qk[Kn][NCOLS];      // 6 x 2048 = 48 KB
    float sc[NH][Kn][Kn];
    float wm[Kn][Kn];
    float contrib[8];
    float smask[8];
    int sidx[8];
    float sinv;
};

__global__ __launch_bounds__(256) void attn_merge_kernel(
    const float* __restrict__ TE,
    const int* __restrict__ idx,
    float* __restrict__ out)
{
    extern __shared__ unsigned char smraw[];
    SmemB* sm = reinterpret_cast<SmemB*>(smraw);

    const int tid = threadIdx.x;
    const int wg = blockIdx.x;     // window id = b*W + w
    const int b = wg >> 7;

    if (tid < Kn) {
        int iv = idx[wg * Kn + tid];
        sm->sidx[tid] = iv;
        sm->smask[tid] = (tid == 0 || iv != 0) ? 1.f : 0.f;
    }

    const float4* src = (const float4*)(g_qk + (size_t)wg * Kn * NCOLS);
    float4* dst = (float4*)sm->qk;
#pragma unroll
    for (int i = 0; i < (Kn * NCOLS / 4) / 256; i++)
        dst[tid + i * 256] = src[tid + i * 256];
    __syncthreads();

    for (int t = tid; t < NH * Kn * Kn; t += 256) {
        int n = t / (Kn * Kn);
        int ij = t % (Kn * Kn);
        int i = ij / Kn, j = ij % Kn;
        const float* qp = &sm->qk[i][n * HD];
        const float* kp = &sm->qk[j][Hn + n * HD];
        float d = 0.f;
#pragma unroll
        for (int dd = 0; dd < HD; dd++) d += qp[dd] * kp[dd];
        sm->sc[n][i][j] = d * 0.125f + sm->smask[i] * sm->smask[j];
    }
    __syncthreads();

    if (tid < NH * Kn) {
        int n = tid / Kn, i = tid % Kn;
        float* row = sm->sc[n][i];
        float mx = row[0];
#pragma unroll
        for (int j = 1; j < Kn; j++) mx = fmaxf(mx, row[j]);
        float e[Kn];
        float s = 0.f;
#pragma unroll
        for (int j = 0; j < Kn; j++) { e[j] = __expf(row[j] - mx); s += e[j]; }
        float inv = 1.f / s;
#pragma unroll
        for (int j = 0; j < Kn; j++) row[j] = e[j] * inv;
    }
    __syncthreads();

    if (tid < Kn * Kn) {
        int i = tid / Kn, j = tid % Kn;
        float s = 0.f;
#pragma unroll
        for (int n = 0; n < NH; n++) s += sm->sc[n][i][j];
        sm->wm[i][j] = s * (1.f / NH);
    }
    __syncthreads();

    if (tid < Kn) {
        int j = tid;
        float c = 0.f;
#pragma unroll
        for (int i = 0; i < Kn; i++)
            c += sm->smask[i] * sm->smask[j] * sm->wm[i][j];
        sm->contrib[j] = c;
    }
    __syncthreads();
    if (tid == 0) {
        float s = 0.f;
#pragma unroll
        for (int j = 0; j < Kn; j++) s += sm->contrib[j];
        sm->sinv = 1.f / (s + 1e-8f);
    }
    __syncthreads();

    float c[Kn];
    float inv = sm->sinv;
#pragma unroll
    for (int kk = 0; kk < Kn; kk++) c[kk] = sm->contrib[kk] * inv;

    const float4* rows[Kn];
#pragma unroll
    for (int kk = 0; kk < Kn; kk++)
        rows[kk] = (const float4*)(TE + ((size_t)b * Sn + sm->sidx[kk]) * Hn);

    float4* orow = (float4*)(out + ((size_t)b * Sn + sm->sidx[0]) * Hn);
    {
        float4 a = make_float4(0.f, 0.f, 0.f, 0.f);
#pragma unroll
        for (int kk = 0; kk < Kn; kk++) {
            float4 v = rows[kk][tid];
            a.x += c[kk] * v.x;
            a.y += c[kk] * v.y;
            a.z += c[kk] * v.z;
            a.w += c[kk] * v.w;
        }
        orow[tid] = a;
    }
}

// ---------------------------------------------------------------------------
extern "C" void kernel_launch(void* const* d_in, const int* in_sizes, int n_in,
                              void* d_out, int out_size)
{
    const float* TE   = (const float*)d_in[0];   // (32,1024,1024) f32
    const float* Wt   = (const float*)d_in[1];   // (3072,1024) f32
    const float* bias = (const float*)d_in[2];   // (3072,) f32
    const int* idx    = (const int*)d_in[3];     // (32,128,6) i32
    float* out = (float*)d_out;

    // Kernel A: cp.async + ldmatrix TF32 projection GEMM into g_qk
    {
        static bool attr_set = false;
        if (!attr_set) {
            cudaFuncSetAttribute(gemm_qk_cp,
                                 cudaFuncAttributeMaxDynamicSharedMemorySize,
                                 GEMM_SMEM);
            attr_set = true;
        }
        dim3 grid(NCOLS / 128, MROWS / 128);   // (16, 192)
        gemm_qk_cp<<<grid, 256, GEMM_SMEM>>>(TE, Wt, bias, idx);
    }

    // Kernel B: copy + zero
    {
        size_t total4 = (size_t)Bn * Sn * Hn / 4;
        copy_zero_kernel<<<(unsigned)(total4 / 256), 256>>>(TE, idx, out);
    }

    // Kernel C: attention + unified scatter (needs out already written)
    {
        static bool attr_set2 = false;
        if (!attr_set2) {
            cudaFuncSetAttribute(attn_merge_kernel,
                                 cudaFuncAttributeMaxDynamicSharedMemorySize,
                                 (int)sizeof(SmemB));
            attr_set2 = true;
        }
        attn_merge_kernel<<<Bn * Wn, 256, sizeof(SmemB)>>>(TE, idx, out);
    }
}

// round 10
// speedup vs baseline: 1.6470x; 1.6470x over previous
#include <cuda_runtime.h>
#include <cuda_fp16.h>
#include <cstdint>

// Problem constants (fixed shapes)
#define Bn 32
#define Sn 1024
#define Hn 1024
#define Wn 128
#define Kn 6
#define NH 16
#define HD 64
#define MROWS (Bn * Wn * Kn)   // 24576
#define NCOLS (2 * Hn)         // 2048

// Scratch: qk projection output (f32), fp16 copies of TE and W[0:2048]
__device__ float g_qk[(size_t)MROWS * NCOLS];
__device__ __half g_TEh[(size_t)Bn * Sn * Hn];    // 64 MB
__device__ __half g_Wh[(size_t)NCOLS * Hn];       // 4 MB

__device__ __forceinline__ uint32_t smem_u32(const void* p) {
    uint32_t a;
    asm("{ .reg .u64 t; cvta.to.shared.u64 t, %1; cvt.u32.u64 %0, t; }" : "=r"(a) : "l"(p));
    return a;
}
__device__ __forceinline__ void mma_f16(float& c0, float& c1, float& c2, float& c3,
                                        uint32_t a0, uint32_t a1, uint32_t a2, uint32_t a3,
                                        uint32_t b0, uint32_t b1)
{
    asm volatile(
        "mma.sync.aligned.m16n8k16.row.col.f32.f16.f16.f32 "
        "{%0,%1,%2,%3},{%4,%5,%6,%7},{%8,%9},{%0,%1,%2,%3};"
        : "+f"(c0), "+f"(c1), "+f"(c2), "+f"(c3)
        : "r"(a0), "r"(a1), "r"(a2), "r"(a3), "r"(b0), "r"(b1));
}
__device__ __forceinline__ void ldsm4(uint32_t& r0, uint32_t& r1, uint32_t& r2, uint32_t& r3,
                                      uint32_t addr)
{
    asm volatile("ldmatrix.sync.aligned.m8n8.x4.shared.b16 {%0,%1,%2,%3}, [%4];"
                 : "=r"(r0), "=r"(r1), "=r"(r2), "=r"(r3) : "r"(addr));
}
__device__ __forceinline__ void cpasync16(uint32_t dst, const void* src, uint32_t sz) {
    asm volatile("cp.async.cg.shared.global [%0], [%1], 16, %2;"
                 :: "r"(dst), "l"(src), "r"(sz) : "memory");
}
#define CP_COMMIT() asm volatile("cp.async.commit_group;" ::: "memory")
#define CP_WAIT(n)  asm volatile("cp.async.wait_group %0;" :: "n"(n) : "memory")
#define SW128(o) ((o) ^ (((o) >> 3) & 0x70))

// ---------------------------------------------------------------------------
// Kernel A: gathered FP16 tensor-core GEMM, cp.async in + ldmatrix out of smem.
//   qk[r][c] = sum_h x[r][h] * W[c][h] + bias[c],  x[r] = mask ? TEh[b,idx[r]] : 0
// Tile 128x128, BK=32 (fp16, 64B rows), 4 stages, 32 iters, 256 threads
// (8 warps 4x2), warp tile 32x64 via mma.m16n8k16.
// SMEM: [0:1024) srcOff, [1024:1536) bias, [2048 + s*16KB) stages (A 8KB | B 8KB)
// ---------------------------------------------------------------------------
#define STAGE_BYTES 16384
#define GEMM_SMEM (2048 + 4 * STAGE_BYTES)

__global__ __launch_bounds__(256, 2) void gemm_qk_f16(
    const float* __restrict__ bias,
    const int* __restrict__ idx)
{
    extern __shared__ unsigned char sm[];
    long long* srcOff = (long long*)sm;
    float* biasSm = (float*)(sm + 1024);
    const uint32_t smBase = smem_u32(sm);

    const int tid = threadIdx.x;
    const int rowBase = blockIdx.y * 128;
    const int colBase = blockIdx.x * 128;

    if (tid < 128) {
        int r = rowBase + tid;
        int b = r / (Wn * Kn);
        int kk = r % Kn;                 // (Wn*Kn) % Kn == 0
        int iv = idx[r];
        bool m = (kk == 0) || (iv != 0);
        srcOff[tid] = m ? ((long long)(b * Sn + iv) * Hn) : -1LL;
        biasSm[tid] = bias[colBase + tid];
    }
    __syncthreads();

    // ---- loader mapping: thread t -> row t>>1, 32B half-row t&1 ----
    const int lrow = tid >> 1;
    const int lhalf = tid & 1;
    const long long aOff = srcOff[lrow];
    const __half* aSrc = g_TEh + (aOff >= 0 ? aOff : 0) + lhalf * 16;   // halves
    const uint32_t aSz = (aOff >= 0) ? 16u : 0u;
    const __half* bSrc = g_Wh + (size_t)(colBase + lrow) * Hn + lhalf * 16;

    const uint32_t dOff = (uint32_t)(lrow * 64 + lhalf * 32);
    const uint32_t aD0 = smBase + 2048 + SW128(dOff);
    const uint32_t aD1 = smBase + 2048 + SW128(dOff + 16);
    const uint32_t bD0 = aD0 + 8192;
    const uint32_t bD1 = aD1 + 8192;

    // ---- compute mapping ----
    const int wid = tid >> 5, lane = tid & 31;
    const int wr = wid >> 1, wc = wid & 1;            // 4 x 2 warp grid
    const int g4 = lane >> 2, t4 = lane & 3;

    // ldmatrix source addresses (stage-0 bases; add stage offset, XOR ks*32)
    uint32_t aLd[2];
    {
        const int rowsel = (lane & 7) + ((lane >> 3) & 1) * 8;
        const uint32_t colHalf = (uint32_t)((lane >> 4) & 1) * 16u;   // k 0-7 / 8-15
#pragma unroll
        for (int mi = 0; mi < 2; mi++) {
            uint32_t o = (uint32_t)((wr * 32 + mi * 16 + rowsel) * 64) + colHalf;
            aLd[mi] = smBase + 2048 + SW128(o);
        }
    }
    uint32_t bLd[4];
    {
        const int rowsel = (lane & 7) + ((lane >> 4) & 1) * 8;
        const uint32_t colHalf = (uint32_t)((lane >> 3) & 1) * 16u;
#pragma unroll
        for (int p = 0; p < 4; p++) {
            uint32_t o = (uint32_t)((wc * 64 + p * 16 + rowsel) * 64) + colHalf;
            bLd[p] = smBase + 2048 + 8192 + SW128(o);
        }
    }

    float acc[2][8][4];
#pragma unroll
    for (int mi = 0; mi < 2; mi++)
#pragma unroll
        for (int ni = 0; ni < 8; ni++)
#pragma unroll
            for (int q = 0; q < 4; q++) acc[mi][ni][q] = 0.f;

    // ---- prologue: prefetch stages 0..2 ----
#pragma unroll
    for (int s = 0; s < 3; s++) {
        const uint32_t sb = (uint32_t)(s * STAGE_BYTES);
        const int k0 = s * 32;                         // halves
        cpasync16(aD0 + sb, aSrc + k0, aSz);
        cpasync16(aD1 + sb, aSrc + k0 + 8, aSz);
        cpasync16(bD0 + sb, bSrc + k0, 16u);
        cpasync16(bD1 + sb, bSrc + k0 + 8, 16u);
        CP_COMMIT();
    }

    // ---- mainloop: 32 iterations of BK=32 (fp16) ----
    for (int it = 0; it < 32; ++it) {
        CP_WAIT(2);
        __syncthreads();

        if (it + 3 < 32) {
            const uint32_t sb = (uint32_t)(((it + 3) & 3) * STAGE_BYTES);
            const int k0 = (it + 3) * 32;
            cpasync16(aD0 + sb, aSrc + k0, aSz);
            cpasync16(aD1 + sb, aSrc + k0 + 8, aSz);
            cpasync16(bD0 + sb, bSrc + k0, 16u);
            cpasync16(bD1 + sb, bSrc + k0 + 8, 16u);
        }
        CP_COMMIT();

        // compute on stage it&3 (two k16 sub-steps)
        const uint32_t sb = (uint32_t)((it & 3) * STAGE_BYTES);
#pragma unroll
        for (int ks = 0; ks < 2; ks++) {
            const uint32_t kx = (uint32_t)(ks * 32);
            uint32_t af[2][4];
#pragma unroll
            for (int mi = 0; mi < 2; mi++)
                ldsm4(af[mi][0], af[mi][1], af[mi][2], af[mi][3],
                      (aLd[mi] + sb) ^ kx);

            uint32_t bf[4][4];   // [p]{b0(2p),b1(2p),b0(2p+1),b1(2p+1)}
#pragma unroll
            for (int p = 0; p < 4; p++)
                ldsm4(bf[p][0], bf[p][1], bf[p][2], bf[p][3],
                      (bLd[p] + sb) ^ kx);

#pragma unroll
            for (int p = 0; p < 4; p++)
#pragma unroll
                for (int h = 0; h < 2; h++) {
                    const int ni = 2 * p + h;
#pragma unroll
                    for (int mi = 0; mi < 2; mi++)
                        mma_f16(acc[mi][ni][0], acc[mi][ni][1], acc[mi][ni][2], acc[mi][ni][3],
                                af[mi][0], af[mi][1], af[mi][2], af[mi][3],
                                bf[p][2 * h], bf[p][2 * h + 1]);
                }
        }
    }

    // ---- epilogue: add bias, store to g_qk ----
#pragma unroll
    for (int mi = 0; mi < 2; mi++) {
        int row0 = rowBase + wr * 32 + mi * 16 + g4;
#pragma unroll
        for (int ni = 0; ni < 8; ni++) {
            int cl = wc * 64 + ni * 8 + t4 * 2;
            float b0 = biasSm[cl], b1 = biasSm[cl + 1];
            float2 v0 = make_float2(acc[mi][ni][0] + b0, acc[mi][ni][1] + b1);
            float2 v1 = make_float2(acc[mi][ni][2] + b0, acc[mi][ni][3] + b1);
            *(float2*)&g_qk[(size_t)row0 * NCOLS + colBase + cl] = v0;
            *(float2*)&g_qk[(size_t)(row0 + 8) * NCOLS + colBase + cl] = v1;
        }
    }
}

// ---------------------------------------------------------------------------
// Kernel B': copy TE -> out (zeroing masked subtoken rows) AND convert TE->fp16.
// ---------------------------------------------------------------------------
__global__ __launch_bounds__(256) void copy_zero_conv_kernel(
    const float* __restrict__ TE,
    const int* __restrict__ idx,
    float* __restrict__ out)
{
    size_t gid = (size_t)blockIdx.x * 256 + threadIdx.x;  // float4 index
    float4 v = ((const float4*)TE)[gid];

    // fp16 conversion (unconditional — GEMM gathers need all rows)
    __half2 h0 = __floats2half2_rn(v.x, v.y);
    __half2 h1 = __floats2half2_rn(v.z, v.w);
    uint2 hv;
    hv.x = *(uint32_t*)&h0;
    hv.y = *(uint32_t*)&h1;
    *(uint2*)(g_TEh + gid * 4) = hv;

    int row = (int)(gid >> 8);        // H/4 = 256 float4 per row
    int b = row >> 10;                // / S
    int s = row & 1023;
    int w = s >> 3;
    int kk = s & 7;
    bool zero = false;
    if (kk < Kn) {
        int iv = idx[(b * Wn + w) * Kn + kk];
        zero = (kk == 0) || (iv != 0);
    }
    if (zero) v = make_float4(0.f, 0.f, 0.f, 0.f);
    ((float4*)out)[gid] = v;
}

// ---------------------------------------------------------------------------
// Kernel W: convert W[0:2048] rows to fp16.
// ---------------------------------------------------------------------------
__global__ __launch_bounds__(256) void conv_w_kernel(const float* __restrict__ Wt)
{
    size_t gid = (size_t)blockIdx.x * 256 + threadIdx.x;  // float4 index over 2048*1024
    float4 v = ((const float4*)Wt)[gid];
    __half2 h0 = __floats2half2_rn(v.x, v.y);
    __half2 h1 = __floats2half2_rn(v.z, v.w);
    uint2 hv;
    hv.x = *(uint32_t*)&h0;
    hv.y = *(uint32_t*)&h1;
    *(uint2*)(g_Wh + gid * 4) = hv;
}

// ---------------------------------------------------------------------------
// Kernel C: per-window attention -> contrib -> unified, scatter to out.
// ---------------------------------------------------------------------------
struct SmemB {
    float qk[Kn][NCOLS];      // 6 x 2048 = 48 KB
    float sc[NH][Kn][Kn];
    float wm[Kn][Kn];
    float contrib[8];
    float smask[8];
    int sidx[8];
    float sinv;
};

__global__ __launch_bounds__(256) void attn_merge_kernel(
    const float* __restrict__ TE,
    const int* __restrict__ idx,
    float* __restrict__ out)
{
    extern __shared__ unsigned char smraw[];
    SmemB* sm = reinterpret_cast<SmemB*>(smraw);

    const int tid = threadIdx.x;
    const int wg = blockIdx.x;     // window id = b*W + w
    const int b = wg >> 7;

    if (tid < Kn) {
        int iv = idx[wg * Kn + tid];
        sm->sidx[tid] = iv;
        sm->smask[tid] = (tid == 0 || iv != 0) ? 1.f : 0.f;
    }

    const float4* src = (const float4*)(g_qk + (size_t)wg * Kn * NCOLS);
    float4* dst = (float4*)sm->qk;
#pragma unroll
    for (int i = 0; i < (Kn * NCOLS / 4) / 256; i++)
        dst[tid + i * 256] = src[tid + i * 256];
    __syncthreads();

    for (int t = tid; t < NH * Kn * Kn; t += 256) {
        int n = t / (Kn * Kn);
        int ij = t % (Kn * Kn);
        int i = ij / Kn, j = ij % Kn;
        const float* qp = &sm->qk[i][n * HD];
        const float* kp = &sm->qk[j][Hn + n * HD];
        float d = 0.f;
#pragma unroll
        for (int dd = 0; dd < HD; dd++) d += qp[dd] * kp[dd];
        sm->sc[n][i][j] = d * 0.125f + sm->smask[i] * sm->smask[j];
    }
    __syncthreads();

    if (tid < NH * Kn) {
        int n = tid / Kn, i = tid % Kn;
        float* row = sm->sc[n][i];
        float mx = row[0];
#pragma unroll
        for (int j = 1; j < Kn; j++) mx = fmaxf(mx, row[j]);
        float e[Kn];
        float s = 0.f;
#pragma unroll
        for (int j = 0; j < Kn; j++) { e[j] = __expf(row[j] - mx); s += e[j]; }
        float inv = 1.f / s;
#pragma unroll
        for (int j = 0; j < Kn; j++) row[j] = e[j] * inv;
    }
    __syncthreads();

    if (tid < Kn * Kn) {
        int i = tid / Kn, j = tid % Kn;
        float s = 0.f;
#pragma unroll
        for (int n = 0; n < NH; n++) s += sm->sc[n][i][j];
        sm->wm[i][j] = s * (1.f / NH);
    }
    __syncthreads();

    if (tid < Kn) {
        int j = tid;
        float c = 0.f;
#pragma unroll
        for (int i = 0; i < Kn; i++)
            c += sm->smask[i] * sm->smask[j] * sm->wm[i][j];
        sm->contrib[j] = c;
    }
    __syncthreads();
    if (tid == 0) {
        float s = 0.f;
#pragma unroll
        for (int j = 0; j < Kn; j++) s += sm->contrib[j];
        sm->sinv = 1.f / (s + 1e-8f);
    }
    __syncthreads();

    float c[Kn];
    float inv = sm->sinv;
#pragma unroll
    for (int kk = 0; kk < Kn; kk++) c[kk] = sm->contrib[kk] * inv;

    const float4* rows[Kn];
#pragma unroll
    for (int kk = 0; kk < Kn; kk++)
        rows[kk] = (const float4*)(TE + ((size_t)b * Sn + sm->sidx[kk]) * Hn);

    float4* orow = (float4*)(out + ((size_t)b * Sn + sm->sidx[0]) * Hn);
    {
        float4 a = make_float4(0.f, 0.f, 0.f, 0.f);
#pragma unroll
        for (int kk = 0; kk < Kn; kk++) {
            float4 v = rows[kk][tid];
            a.x += c[kk] * v.x;
            a.y += c[kk] * v.y;
            a.z += c[kk] * v.z;
            a.w += c[kk] * v.w;
        }
        orow[tid] = a;
    }
}

// ---------------------------------------------------------------------------
extern "C" void kernel_launch(void* const* d_in, const int* in_sizes, int n_in,
                              void* d_out, int out_size)
{
    const float* TE   = (const float*)d_in[0];   // (32,1024,1024) f32
    const float* Wt   = (const float*)d_in[1];   // (3072,1024) f32
    const float* bias = (const float*)d_in[2];   // (3072,) f32
    const int* idx    = (const int*)d_in[3];     // (32,128,6) i32
    float* out = (float*)d_out;

    // Kernel B': copy+zero AND TE->fp16 conversion (produces g_TEh)
    {
        size_t total4 = (size_t)Bn * Sn * Hn / 4;   // 8388608
        copy_zero_conv_kernel<<<(unsigned)(total4 / 256), 256>>>(TE, idx, out);
    }

    // Kernel W: W[0:2048] -> fp16 (produces g_Wh)
    {
        size_t total4 = (size_t)NCOLS * Hn / 4;     // 524288
        conv_w_kernel<<<(unsigned)(total4 / 256), 256>>>(Wt);
    }

    // Kernel A: fp16 tensor-core projection GEMM into g_qk
    {
        static bool attr_set = false;
        if (!attr_set) {
            cudaFuncSetAttribute(gemm_qk_f16,
                                 cudaFuncAttributeMaxDynamicSharedMemorySize,
                                 GEMM_SMEM);
            attr_set = true;
        }
        dim3 grid(NCOLS / 128, MROWS / 128);   // (16, 192)
        gemm_qk_f16<<<grid, 256, GEMM_SMEM>>>(bias, idx);
    }

    // Kernel C: attention + unified scatter (needs out + g_qk)
    {
        static bool attr_set2 = false;
        if (!attr_set2) {
            cudaFuncSetAttribute(attn_merge_kernel,
                                 cudaFuncAttributeMaxDynamicSharedMemorySize,
                                 (int)sizeof(SmemB));
            attr_set2 = true;
        }
        attn_merge_kernel<<<Bn * Wn, 256, sizeof(SmemB)>>>(TE, idx, out);
    }
}

// round 12
// speedup vs baseline: 1.9555x; 1.1873x over previous
#include <cuda_runtime.h>
#include <cuda_fp16.h>
#include <cstdint>

// Problem constants (fixed shapes)
#define Bn 32
#define Sn 1024
#define Hn 1024
#define Wn 128
#define Kn 6
#define NH 16
#define HD 64
#define MROWS (Bn * Wn * Kn)   // 24576
#define NCOLS (2 * Hn)         // 2048

// Scratch: qk projection output (f32), fp16 copies of TE and W[0:2048]
__device__ float g_qk[(size_t)MROWS * NCOLS];
__device__ __half g_TEh[(size_t)Bn * Sn * Hn];    // 64 MB
__device__ __half g_Wh[(size_t)NCOLS * Hn];       // 4 MB

__device__ __forceinline__ uint32_t smem_u32(const void* p) {
    uint32_t a;
    asm("{ .reg .u64 t; cvta.to.shared.u64 t, %1; cvt.u32.u64 %0, t; }" : "=r"(a) : "l"(p));
    return a;
}
__device__ __forceinline__ void mma_f16(float& c0, float& c1, float& c2, float& c3,
                                        uint32_t a0, uint32_t a1, uint32_t a2, uint32_t a3,
                                        uint32_t b0, uint32_t b1)
{
    asm volatile(
        "mma.sync.aligned.m16n8k16.row.col.f32.f16.f16.f32 "
        "{%0,%1,%2,%3},{%4,%5,%6,%7},{%8,%9},{%0,%1,%2,%3};"
        : "+f"(c0), "+f"(c1), "+f"(c2), "+f"(c3)
        : "r"(a0), "r"(a1), "r"(a2), "r"(a3), "r"(b0), "r"(b1));
}
__device__ __forceinline__ void ldsm4(uint32_t& r0, uint32_t& r1, uint32_t& r2, uint32_t& r3,
                                      uint32_t addr)
{
    asm volatile("ldmatrix.sync.aligned.m8n8.x4.shared.b16 {%0,%1,%2,%3}, [%4];"
                 : "=r"(r0), "=r"(r1), "=r"(r2), "=r"(r3) : "r"(addr));
}
__device__ __forceinline__ void cpasync16(uint32_t dst, const void* src, uint32_t sz) {
    asm volatile("cp.async.cg.shared.global [%0], [%1], 16, %2;"
                 :: "r"(dst), "l"(src), "r"(sz) : "memory");
}
#define CP_COMMIT() asm volatile("cp.async.commit_group;" ::: "memory")
#define CP_WAIT(n)  asm volatile("cp.async.wait_group %0;" :: "n"(n) : "memory")
#define SW128(o) ((o) ^ (((o) >> 3) & 0x70))

// ---------------------------------------------------------------------------
// Kernel A: gathered FP16 tensor-core GEMM, cp.async in + ldmatrix out of smem.
//   qk[r][c] = sum_h x[r][h] * W[c][h] + bias[c],  x[r] = mask ? TEh[b,idx[r]] : 0
// Tile 128x128, BK=32 (fp16, 64B rows), 4 stages, 32 iters, 256 threads
// (8 warps 4x2), warp tile 32x64 via mma.m16n8k16.
// SMEM: [0:1024) srcOff, [1024:1536) bias, [2048 + s*16KB) stages (A 8KB | B 8KB)
// ---------------------------------------------------------------------------
#define STAGE_BYTES 16384
#define GEMM_SMEM (2048 + 4 * STAGE_BYTES)

__global__ __launch_bounds__(256, 2) void gemm_qk_f16(
    const float* __restrict__ bias,
    const int* __restrict__ idx)
{
    extern __shared__ unsigned char sm[];
    long long* srcOff = (long long*)sm;
    float* biasSm = (float*)(sm + 1024);
    const uint32_t smBase = smem_u32(sm);

    const int tid = threadIdx.x;
    const int rowBase = blockIdx.y * 128;
    const int colBase = blockIdx.x * 128;

    if (tid < 128) {
        int r = rowBase + tid;
        int b = r / (Wn * Kn);
        int kk = r % Kn;                 // (Wn*Kn) % Kn == 0
        int iv = idx[r];
        bool m = (kk == 0) || (iv != 0);
        srcOff[tid] = m ? ((long long)(b * Sn + iv) * Hn) : -1LL;
        biasSm[tid] = bias[colBase + tid];
    }
    __syncthreads();

    // ---- loader mapping: thread t -> row t>>1, 32B half-row t&1 ----
    const int lrow = tid >> 1;
    const int lhalf = tid & 1;
    const long long aOff = srcOff[lrow];
    const __half* aSrc = g_TEh + (aOff >= 0 ? aOff : 0) + lhalf * 16;   // halves
    const uint32_t aSz = (aOff >= 0) ? 16u : 0u;
    const __half* bSrc = g_Wh + (size_t)(colBase + lrow) * Hn + lhalf * 16;

    const uint32_t dOff = (uint32_t)(lrow * 64 + lhalf * 32);
    const uint32_t aD0 = smBase + 2048 + SW128(dOff);
    const uint32_t aD1 = smBase + 2048 + SW128(dOff + 16);
    const uint32_t bD0 = aD0 + 8192;
    const uint32_t bD1 = aD1 + 8192;

    // ---- compute mapping ----
    const int wid = tid >> 5, lane = tid & 31;
    const int wr = wid >> 1, wc = wid & 1;            // 4 x 2 warp grid
    const int g4 = lane >> 2, t4 = lane & 3;

    // ldmatrix source addresses (stage-0 bases; add stage offset, XOR ks*32)
    uint32_t aLd[2];
    {
        const int rowsel = (lane & 7) + ((lane >> 3) & 1) * 8;
        const uint32_t colHalf = (uint32_t)((lane >> 4) & 1) * 16u;   // k 0-7 / 8-15
#pragma unroll
        for (int mi = 0; mi < 2; mi++) {
            uint32_t o = (uint32_t)((wr * 32 + mi * 16 + rowsel) * 64) + colHalf;
            aLd[mi] = smBase + 2048 + SW128(o);
        }
    }
    uint32_t bLd[4];
    {
        const int rowsel = (lane & 7) + ((lane >> 4) & 1) * 8;
        const uint32_t colHalf = (uint32_t)((lane >> 3) & 1) * 16u;
#pragma unroll
        for (int p = 0; p < 4; p++) {
            uint32_t o = (uint32_t)((wc * 64 + p * 16 + rowsel) * 64) + colHalf;
            bLd[p] = smBase + 2048 + 8192 + SW128(o);
        }
    }

    float acc[2][8][4];
#pragma unroll
    for (int mi = 0; mi < 2; mi++)
#pragma unroll
        for (int ni = 0; ni < 8; ni++)
#pragma unroll
            for (int q = 0; q < 4; q++) acc[mi][ni][q] = 0.f;

    // ---- prologue: prefetch stages 0..2 ----
#pragma unroll
    for (int s = 0; s < 3; s++) {
        const uint32_t sb = (uint32_t)(s * STAGE_BYTES);
        const int k0 = s * 32;                         // halves
        cpasync16(aD0 + sb, aSrc + k0, aSz);
        cpasync16(aD1 + sb, aSrc + k0 + 8, aSz);
        cpasync16(bD0 + sb, bSrc + k0, 16u);
        cpasync16(bD1 + sb, bSrc + k0 + 8, 16u);
        CP_COMMIT();
    }

    // ---- mainloop: 32 iterations of BK=32 (fp16) ----
    for (int it = 0; it < 32; ++it) {
        CP_WAIT(2);
        __syncthreads();

        if (it + 3 < 32) {
            const uint32_t sb = (uint32_t)(((it + 3) & 3) * STAGE_BYTES);
            const int k0 = (it + 3) * 32;
            cpasync16(aD0 + sb, aSrc + k0, aSz);
            cpasync16(aD1 + sb, aSrc + k0 + 8, aSz);
            cpasync16(bD0 + sb, bSrc + k0, 16u);
            cpasync16(bD1 + sb, bSrc + k0 + 8, 16u);
        }
        CP_COMMIT();

        // compute on stage it&3 (two k16 sub-steps)
        const uint32_t sb = (uint32_t)((it & 3) * STAGE_BYTES);
#pragma unroll
        for (int ks = 0; ks < 2; ks++) {
            const uint32_t kx = (uint32_t)(ks * 32);
            uint32_t af[2][4];
#pragma unroll
            for (int mi = 0; mi < 2; mi++)
                ldsm4(af[mi][0], af[mi][1], af[mi][2], af[mi][3],
                      (aLd[mi] + sb) ^ kx);

            uint32_t bf[4][4];   // [p]{b0(2p),b1(2p),b0(2p+1),b1(2p+1)}
#pragma unroll
            for (int p = 0; p < 4; p++)
                ldsm4(bf[p][0], bf[p][1], bf[p][2], bf[p][3],
                      (bLd[p] + sb) ^ kx);

#pragma unroll
            for (int p = 0; p < 4; p++)
#pragma unroll
                for (int h = 0; h < 2; h++) {
                    const int ni = 2 * p + h;
#pragma unroll
                    for (int mi = 0; mi < 2; mi++)
                        mma_f16(acc[mi][ni][0], acc[mi][ni][1], acc[mi][ni][2], acc[mi][ni][3],
                                af[mi][0], af[mi][1], af[mi][2], af[mi][3],
                                bf[p][2 * h], bf[p][2 * h + 1]);
                }
        }
    }

    // ---- epilogue: add bias, store to g_qk ----
#pragma unroll
    for (int mi = 0; mi < 2; mi++) {
        int row0 = rowBase + wr * 32 + mi * 16 + g4;
#pragma unroll
        for (int ni = 0; ni < 8; ni++) {
            int cl = wc * 64 + ni * 8 + t4 * 2;
            float b0 = biasSm[cl], b1 = biasSm[cl + 1];
            float2 v0 = make_float2(acc[mi][ni][0] + b0, acc[mi][ni][1] + b1);
            float2 v1 = make_float2(acc[mi][ni][2] + b0, acc[mi][ni][3] + b1);
            *(float2*)&g_qk[(size_t)row0 * NCOLS + colBase + cl] = v0;
            *(float2*)&g_qk[(size_t)(row0 + 8) * NCOLS + colBase + cl] = v1;
        }
    }
}

// ---------------------------------------------------------------------------
// Kernel B': copy TE -> out (zeroing masked subtoken rows) AND convert TE->fp16.
// ---------------------------------------------------------------------------
__global__ __launch_bounds__(256) void copy_zero_conv_kernel(
    const float* __restrict__ TE,
    const int* __restrict__ idx,
    float* __restrict__ out)
{
    size_t gid = (size_t)blockIdx.x * 256 + threadIdx.x;  // float4 index
    float4 v = ((const float4*)TE)[gid];

    // fp16 conversion (unconditional — GEMM gathers need all rows)
    __half2 h0 = __floats2half2_rn(v.x, v.y);
    __half2 h1 = __floats2half2_rn(v.z, v.w);
    uint2 hv;
    hv.x = *(uint32_t*)&h0;
    hv.y = *(uint32_t*)&h1;
    *(uint2*)(g_TEh + gid * 4) = hv;

    int row = (int)(gid >> 8);        // H/4 = 256 float4 per row
    int b = row >> 10;                // / S
    int s = row & 1023;
    int w = s >> 3;
    int kk = s & 7;
    bool zero = false;
    if (kk < Kn) {
        int iv = idx[(b * Wn + w) * Kn + kk];
        zero = (kk == 0) || (iv != 0);
    }
    if (zero) v = make_float4(0.f, 0.f, 0.f, 0.f);
    ((float4*)out)[gid] = v;
}

// ---------------------------------------------------------------------------
// Kernel W: convert W[0:2048] rows to fp16.
// ---------------------------------------------------------------------------
__global__ __launch_bounds__(256) void conv_w_kernel(const float* __restrict__ Wt)
{
    size_t gid = (size_t)blockIdx.x * 256 + threadIdx.x;  // float4 index over 2048*1024
    float4 v = ((const float4*)Wt)[gid];
    __half2 h0 = __floats2half2_rn(v.x, v.y);
    __half2 h1 = __floats2half2_rn(v.z, v.w);
    uint2 hv;
    hv.x = *(uint32_t*)&h0;
    hv.y = *(uint32_t*)&h1;
    *(uint2*)(g_Wh + gid * 4) = hv;
}

// ---------------------------------------------------------------------------
// Kernel C: per-window attention -> contrib -> unified, scatter to out.
// qk rows padded to 2056 floats (+8) so row stride is 8 banks, killing the
// 32-way LDS conflicts of the unpadded 2048-float stride. Dots use float4.
// ---------------------------------------------------------------------------
#define QKSTRIDE (NCOLS + 8)      // 2056 floats, 8224 B (16B-aligned)

struct SmemB {
    float qk[Kn][QKSTRIDE];   // ~48.2 KB
    float sc[NH][Kn][Kn];
    float wm[Kn][Kn];
    float contrib[8];
    float smask[8];
    int sidx[8];
    float sinv;
};

__global__ __launch_bounds__(256) void attn_merge_kernel(
    const float* __restrict__ TE,
    const int* __restrict__ idx,
    float* __restrict__ out)
{
    extern __shared__ unsigned char smraw[];
    SmemB* sm = reinterpret_cast<SmemB*>(smraw);

    const int tid = threadIdx.x;
    const int wg = blockIdx.x;     // window id = b*W + w
    const int b = wg >> 7;

    if (tid < Kn) {
        int iv = idx[wg * Kn + tid];
        sm->sidx[tid] = iv;
        sm->smask[tid] = (tid == 0 || iv != 0) ? 1.f : 0.f;
    }

    // Load 6 x 2048 qk rows into padded smem rows (512 float4 per row)
    {
        const float4* src = (const float4*)(g_qk + (size_t)wg * Kn * NCOLS);
#pragma unroll
        for (int r = 0; r < Kn; r++) {
            float4* dst = (float4*)&sm->qk[r][0];
            const float4* s4 = src + r * (NCOLS / 4);
#pragma unroll
            for (int i = 0; i < (NCOLS / 4) / 256; i++)
                dst[tid + i * 256] = s4[tid + i * 256];
        }
    }
    __syncthreads();

    // Scores: 16 heads x 6 x 6 = 576 dot(64) tasks, float4 vectorized
    for (int t = tid; t < NH * Kn * Kn; t += 256) {
        int n = t / (Kn * Kn);
        int ij = t % (Kn * Kn);
        int i = ij / Kn, j = ij % Kn;
        const float4* qp = (const float4*)&sm->qk[i][n * HD];
        const float4* kp = (const float4*)&sm->qk[j][Hn + n * HD];
        float d = 0.f;
#pragma unroll
        for (int dd = 0; dd < HD / 4; dd++) {
            float4 a = qp[dd];
            float4 bb = kp[dd];
            d += a.x * bb.x + a.y * bb.y + a.z * bb.z + a.w * bb.w;
        }
        sm->sc[n][i][j] = d * 0.125f + sm->smask[i] * sm->smask[j];
    }
    __syncthreads();

    if (tid < NH * Kn) {
        int n = tid / Kn, i = tid % Kn;
        float* row = sm->sc[n][i];
        float mx = row[0];
#pragma unroll
        for (int j = 1; j < Kn; j++) mx = fmaxf(mx, row[j]);
        float e[Kn];
        float s = 0.f;
#pragma unroll
        for (int j = 0; j < Kn; j++) { e[j] = __expf(row[j] - mx); s += e[j]; }
        float inv = 1.f / s;
#pragma unroll
        for (int j = 0; j < Kn; j++) row[j] = e[j] * inv;
    }
    __syncthreads();

    if (tid < Kn * Kn) {
        int i = tid / Kn, j = tid % Kn;
        float s = 0.f;
#pragma unroll
        for (int n = 0; n < NH; n++) s += sm->sc[n][i][j];
        sm->wm[i][j] = s * (1.f / NH);
    }
    __syncthreads();

    if (tid < Kn) {
        int j = tid;
        float c = 0.f;
#pragma unroll
        for (int i = 0; i < Kn; i++)
            c += sm->smask[i] * sm->smask[j] * sm->wm[i][j];
        sm->contrib[j] = c;
    }
    __syncthreads();
    if (tid == 0) {
        float s = 0.f;
#pragma unroll
        for (int j = 0; j < Kn; j++) s += sm->contrib[j];
        sm->sinv = 1.f / (s + 1e-8f);
    }
    __syncthreads();

    float c[Kn];
    float inv = sm->sinv;
#pragma unroll
    for (int kk = 0; kk < Kn; kk++) c[kk] = sm->contrib[kk] * inv;

    const float4* rows[Kn];
#pragma unroll
    for (int kk = 0; kk < Kn; kk++)
        rows[kk] = (const float4*)(TE + ((size_t)b * Sn + sm->sidx[kk]) * Hn);

    float4* orow = (float4*)(out + ((size_t)b * Sn + sm->sidx[0]) * Hn);
    {
        float4 a = make_float4(0.f, 0.f, 0.f, 0.f);
#pragma unroll
        for (int kk = 0; kk < Kn; kk++) {
            float4 v = rows[kk][tid];
            a.x += c[kk] * v.x;
            a.y += c[kk] * v.y;
            a.z += c[kk] * v.z;
            a.w += c[kk] * v.w;
        }
        orow[tid] = a;
    }
}

// ---------------------------------------------------------------------------
extern "C" void kernel_launch(void* const* d_in, const int* in_sizes, int n_in,
                              void* d_out, int out_size)
{
    const float* TE   = (const float*)d_in[0];   // (32,1024,1024) f32
    const float* Wt   = (const float*)d_in[1];   // (3072,1024) f32
    const float* bias = (const float*)d_in[2];   // (3072,) f32
    const int* idx    = (const int*)d_in[3];     // (32,128,6) i32
    float* out = (float*)d_out;

    // Kernel B': copy+zero AND TE->fp16 conversion (produces g_TEh)
    {
        size_t total4 = (size_t)Bn * Sn * Hn / 4;   // 8388608
        copy_zero_conv_kernel<<<(unsigned)(total4 / 256), 256>>>(TE, idx, out);
    }

    // Kernel W: W[0:2048] -> fp16 (produces g_Wh)
    {
        size_t total4 = (size_t)NCOLS * Hn / 4;     // 524288
        conv_w_kernel<<<(unsigned)(total4 / 256), 256>>>(Wt);
    }

    // Kernel A: fp16 tensor-core projection GEMM into g_qk
    {
        static bool attr_set = false;
        if (!attr_set) {
            cudaFuncSetAttribute(gemm_qk_f16,
                                 cudaFuncAttributeMaxDynamicSharedMemorySize,
                                 GEMM_SMEM);
            attr_set = true;
        }
        dim3 grid(NCOLS / 128, MROWS / 128);   // (16, 192)
        gemm_qk_f16<<<grid, 256, GEMM_SMEM>>>(bias, idx);
    }

    // Kernel C: attention + unified scatter (needs out + g_qk)
    {
        static bool attr_set2 = false;
        if (!attr_set2) {
            cudaFuncSetAttribute(attn_merge_kernel,
                                 cudaFuncAttributeMaxDynamicSharedMemorySize,
                                 (int)sizeof(SmemB));
            attr_set2 = true;
        }
        attn_merge_kernel<<<Bn * Wn, 256, sizeof(SmemB)>>>(TE, idx, out);
    }
}

// round 13
// speedup vs baseline: 2.1257x; 1.0871x over previous
#include <cuda_runtime.h>
#include <cuda_fp16.h>
#include <cstdint>

// Problem constants (fixed shapes)
#define Bn 32
#define Sn 1024
#define Hn 1024
#define Wn 128
#define Kn 6
#define NH 16
#define HD 64
#define MROWS (Bn * Wn * Kn)   // 24576
#define NCOLS (2 * Hn)         // 2048

// Scratch: qk projection output (fp16), fp16 copies of TE and W[0:2048]
__device__ __half g_qkh[(size_t)MROWS * NCOLS];   // 100 MB
__device__ __half g_TEh[(size_t)Bn * Sn * Hn];    // 64 MB
__device__ __half g_Wh[(size_t)NCOLS * Hn];       // 4 MB

__device__ __forceinline__ uint32_t smem_u32(const void* p) {
    uint32_t a;
    asm("{ .reg .u64 t; cvta.to.shared.u64 t, %1; cvt.u32.u64 %0, t; }" : "=r"(a) : "l"(p));
    return a;
}
__device__ __forceinline__ void mma_f16(float& c0, float& c1, float& c2, float& c3,
                                        uint32_t a0, uint32_t a1, uint32_t a2, uint32_t a3,
                                        uint32_t b0, uint32_t b1)
{
    asm volatile(
        "mma.sync.aligned.m16n8k16.row.col.f32.f16.f16.f32 "
        "{%0,%1,%2,%3},{%4,%5,%6,%7},{%8,%9},{%0,%1,%2,%3};"
        : "+f"(c0), "+f"(c1), "+f"(c2), "+f"(c3)
        : "r"(a0), "r"(a1), "r"(a2), "r"(a3), "r"(b0), "r"(b1));
}
__device__ __forceinline__ void ldsm4(uint32_t& r0, uint32_t& r1, uint32_t& r2, uint32_t& r3,
                                      uint32_t addr)
{
    asm volatile("ldmatrix.sync.aligned.m8n8.x4.shared.b16 {%0,%1,%2,%3}, [%4];"
                 : "=r"(r0), "=r"(r1), "=r"(r2), "=r"(r3) : "r"(addr));
}
__device__ __forceinline__ void cpasync16(uint32_t dst, const void* src, uint32_t sz) {
    asm volatile("cp.async.cg.shared.global [%0], [%1], 16, %2;"
                 :: "r"(dst), "l"(src), "r"(sz) : "memory");
}
#define CP_COMMIT() asm volatile("cp.async.commit_group;" ::: "memory")
#define CP_WAIT(n)  asm volatile("cp.async.wait_group %0;" :: "n"(n) : "memory")
#define SW128(o) ((o) ^ (((o) >> 3) & 0x70))

// ---------------------------------------------------------------------------
// Kernel A: gathered FP16 tensor-core GEMM, cp.async in + ldmatrix out of smem.
//   qk[r][c] = sum_h x[r][h] * W[c][h] + bias[c],  x[r] = mask ? TEh[b,idx[r]] : 0
// Tile 128x128, BK=32 (fp16, 64B rows), 6 stages, 32 iters, 256 threads
// (8 warps 4x2), warp tile 32x64 via mma.m16n8k16. Output fp16.
// SMEM: [0:1024) srcOff, [1024:1536) bias, [2048 + s*16KB) stages (A 8KB | B 8KB)
// ---------------------------------------------------------------------------
#define STAGE_BYTES 16384
#define NSTAGE 6
#define GEMM_SMEM (2048 + NSTAGE * STAGE_BYTES)

__global__ __launch_bounds__(256, 2) void gemm_qk_f16(
    const float* __restrict__ bias,
    const int* __restrict__ idx)
{
    extern __shared__ unsigned char sm[];
    long long* srcOff = (long long*)sm;
    float* biasSm = (float*)(sm + 1024);
    const uint32_t smBase = smem_u32(sm);

    const int tid = threadIdx.x;
    const int rowBase = blockIdx.y * 128;
    const int colBase = blockIdx.x * 128;

    if (tid < 128) {
        int r = rowBase + tid;
        int b = r / (Wn * Kn);
        int kk = r % Kn;                 // (Wn*Kn) % Kn == 0
        int iv = idx[r];
        bool m = (kk == 0) || (iv != 0);
        srcOff[tid] = m ? ((long long)(b * Sn + iv) * Hn) : -1LL;
        biasSm[tid] = bias[colBase + tid];
    }
    __syncthreads();

    // ---- loader mapping: thread t -> row t>>1, 32B half-row t&1 ----
    const int lrow = tid >> 1;
    const int lhalf = tid & 1;
    const long long aOff = srcOff[lrow];
    const __half* aSrc = g_TEh + (aOff >= 0 ? aOff : 0) + lhalf * 16;   // halves
    const uint32_t aSz = (aOff >= 0) ? 16u : 0u;
    const __half* bSrc = g_Wh + (size_t)(colBase + lrow) * Hn + lhalf * 16;

    const uint32_t dOff = (uint32_t)(lrow * 64 + lhalf * 32);
    const uint32_t aD0 = smBase + 2048 + SW128(dOff);
    const uint32_t aD1 = smBase + 2048 + SW128(dOff + 16);
    const uint32_t bD0 = aD0 + 8192;
    const uint32_t bD1 = aD1 + 8192;

    // ---- compute mapping ----
    const int wid = tid >> 5, lane = tid & 31;
    const int wr = wid >> 1, wc = wid & 1;            // 4 x 2 warp grid
    const int g4 = lane >> 2, t4 = lane & 3;

    // ldmatrix source addresses (stage-0 bases; add stage offset, XOR ks*32)
    uint32_t aLd[2];
    {
        const int rowsel = (lane & 7) + ((lane >> 3) & 1) * 8;
        const uint32_t colHalf = (uint32_t)((lane >> 4) & 1) * 16u;   // k 0-7 / 8-15
#pragma unroll
        for (int mi = 0; mi < 2; mi++) {
            uint32_t o = (uint32_t)((wr * 32 + mi * 16 + rowsel) * 64) + colHalf;
            aLd[mi] = smBase + 2048 + SW128(o);
        }
    }
    uint32_t bLd[4];
    {
        const int rowsel = (lane & 7) + ((lane >> 4) & 1) * 8;
        const uint32_t colHalf = (uint32_t)((lane >> 3) & 1) * 16u;
#pragma unroll
        for (int p = 0; p < 4; p++) {
            uint32_t o = (uint32_t)((wc * 64 + p * 16 + rowsel) * 64) + colHalf;
            bLd[p] = smBase + 2048 + 8192 + SW128(o);
        }
    }

    float acc[2][8][4];
#pragma unroll
    for (int mi = 0; mi < 2; mi++)
#pragma unroll
        for (int ni = 0; ni < 8; ni++)
#pragma unroll
            for (int q = 0; q < 4; q++) acc[mi][ni][q] = 0.f;

    // ---- prologue: prefetch stages 0..4 ----
#pragma unroll
    for (int s = 0; s < NSTAGE - 1; s++) {
        const uint32_t sb = (uint32_t)(s * STAGE_BYTES);
        const int k0 = s * 32;                         // halves
        cpasync16(aD0 + sb, aSrc + k0, aSz);
        cpasync16(aD1 + sb, aSrc + k0 + 8, aSz);
        cpasync16(bD0 + sb, bSrc + k0, 16u);
        cpasync16(bD1 + sb, bSrc + k0 + 8, 16u);
        CP_COMMIT();
    }

    // ---- mainloop: 32 iterations of BK=32 (fp16) ----
    for (int it = 0; it < 32; ++it) {
        CP_WAIT(4);
        __syncthreads();

        // prefetch stage it+5 (reuses buffer of it-1; safe post-barrier)
        if (it + NSTAGE - 1 < 32) {
            const uint32_t sb = (uint32_t)(((it + NSTAGE - 1) % NSTAGE) * STAGE_BYTES);
            const int k0 = (it + NSTAGE - 1) * 32;
            cpasync16(aD0 + sb, aSrc + k0, aSz);
            cpasync16(aD1 + sb, aSrc + k0 + 8, aSz);
            cpasync16(bD0 + sb, bSrc + k0, 16u);
            cpasync16(bD1 + sb, bSrc + k0 + 8, 16u);
        }
        CP_COMMIT();

        // compute on stage it%NSTAGE (two k16 sub-steps)
        const uint32_t sb = (uint32_t)((it % NSTAGE) * STAGE_BYTES);
#pragma unroll
        for (int ks = 0; ks < 2; ks++) {
            const uint32_t kx = (uint32_t)(ks * 32);
            uint32_t af[2][4];
#pragma unroll
            for (int mi = 0; mi < 2; mi++)
                ldsm4(af[mi][0], af[mi][1], af[mi][2], af[mi][3],
                      (aLd[mi] + sb) ^ kx);

            uint32_t bf[4][4];   // [p]{b0(2p),b1(2p),b0(2p+1),b1(2p+1)}
#pragma unroll
            for (int p = 0; p < 4; p++)
                ldsm4(bf[p][0], bf[p][1], bf[p][2], bf[p][3],
                      (bLd[p] + sb) ^ kx);

#pragma unroll
            for (int p = 0; p < 4; p++)
#pragma unroll
                for (int h = 0; h < 2; h++) {
                    const int ni = 2 * p + h;
#pragma unroll
                    for (int mi = 0; mi < 2; mi++)
                        mma_f16(acc[mi][ni][0], acc[mi][ni][1], acc[mi][ni][2], acc[mi][ni][3],
                                af[mi][0], af[mi][1], af[mi][2], af[mi][3],
                                bf[p][2 * h], bf[p][2 * h + 1]);
                }
        }
    }

    // ---- epilogue: add bias, convert to fp16, store to g_qkh ----
#pragma unroll
    for (int mi = 0; mi < 2; mi++) {
        int row0 = rowBase + wr * 32 + mi * 16 + g4;
#pragma unroll
        for (int ni = 0; ni < 8; ni++) {
            int cl = wc * 64 + ni * 8 + t4 * 2;
            float b0 = biasSm[cl], b1 = biasSm[cl + 1];
            __half2 v0 = __floats2half2_rn(acc[mi][ni][0] + b0, acc[mi][ni][1] + b1);
            __half2 v1 = __floats2half2_rn(acc[mi][ni][2] + b0, acc[mi][ni][3] + b1);
            *(__half2*)&g_qkh[(size_t)row0 * NCOLS + colBase + cl] = v0;
            *(__half2*)&g_qkh[(size_t)(row0 + 8) * NCOLS + colBase + cl] = v1;
        }
    }
}

// ---------------------------------------------------------------------------
// Kernel B': copy TE -> out (zeroing masked subtoken rows) AND convert TE->fp16.
// ---------------------------------------------------------------------------
__global__ __launch_bounds__(256) void copy_zero_conv_kernel(
    const float* __restrict__ TE,
    const int* __restrict__ idx,
    float* __restrict__ out)
{
    size_t gid = (size_t)blockIdx.x * 256 + threadIdx.x;  // float4 index
    float4 v = ((const float4*)TE)[gid];

    // fp16 conversion (unconditional — GEMM gathers need all rows)
    __half2 h0 = __floats2half2_rn(v.x, v.y);
    __half2 h1 = __floats2half2_rn(v.z, v.w);
    uint2 hv;
    hv.x = *(uint32_t*)&h0;
    hv.y = *(uint32_t*)&h1;
    *(uint2*)(g_TEh + gid * 4) = hv;

    int row = (int)(gid >> 8);        // H/4 = 256 float4 per row
    int b = row >> 10;                // / S
    int s = row & 1023;
    int w = s >> 3;
    int kk = s & 7;
    bool zero = false;
    if (kk < Kn) {
        int iv = idx[(b * Wn + w) * Kn + kk];
        zero = (kk == 0) || (iv != 0);
    }
    if (zero) v = make_float4(0.f, 0.f, 0.f, 0.f);
    ((float4*)out)[gid] = v;
}

// ---------------------------------------------------------------------------
// Kernel W: convert W[0:2048] rows to fp16.
// ---------------------------------------------------------------------------
__global__ __launch_bounds__(256) void conv_w_kernel(const float* __restrict__ Wt)
{
    size_t gid = (size_t)blockIdx.x * 256 + threadIdx.x;  // float4 index over 2048*1024
    float4 v = ((const float4*)Wt)[gid];
    __half2 h0 = __floats2half2_rn(v.x, v.y);
    __half2 h1 = __floats2half2_rn(v.z, v.w);
    uint2 hv;
    hv.x = *(uint32_t*)&h0;
    hv.y = *(uint32_t*)&h1;
    *(uint2*)(g_Wh + gid * 4) = hv;
}

// ---------------------------------------------------------------------------
// Kernel C: per-window attention -> contrib -> unified, scatter to out.
// qk held in fp16 in smem, rows padded +16 halves (32B) to break the
// 32-bank row-stride conflicts; score dots convert half2->float and FFMA.
// ---------------------------------------------------------------------------
#define QKSTRIDE_H (NCOLS + 16)   // 2064 halves = 4128 B per row

struct SmemB {
    __half qk[Kn][QKSTRIDE_H];    // ~24.2 KB
    float sc[NH][Kn][Kn];
    float wm[Kn][Kn];
    float contrib[8];
    float smask[8];
    int sidx[8];
    float sinv;
};

__global__ __launch_bounds__(256) void attn_merge_kernel(
    const float* __restrict__ TE,
    const int* __restrict__ idx,
    float* __restrict__ out)
{
    extern __shared__ unsigned char smraw[];
    SmemB* sm = reinterpret_cast<SmemB*>(smraw);

    const int tid = threadIdx.x;
    const int wg = blockIdx.x;     // window id = b*W + w
    const int b = wg >> 7;

    if (tid < Kn) {
        int iv = idx[wg * Kn + tid];
        sm->sidx[tid] = iv;
        sm->smask[tid] = (tid == 0 || iv != 0) ? 1.f : 0.f;
    }

    // Load 6 x 2048 fp16 qk rows (256 uint4 per row, one per thread)
    {
        const __half* src = g_qkh + (size_t)wg * Kn * NCOLS;
#pragma unroll
        for (int r = 0; r < Kn; r++) {
            ((uint4*)&sm->qk[r][0])[tid] = ((const uint4*)(src + r * NCOLS))[tid];
        }
    }
    __syncthreads();

    // Scores: 16 heads x 6 x 6 = 576 dot(64) tasks (fp16 operands, f32 accum)
    for (int t = tid; t < NH * Kn * Kn; t += 256) {
        int n = t / (Kn * Kn);
        int ij = t % (Kn * Kn);
        int i = ij / Kn, j = ij % Kn;
        const uint4* qp = (const uint4*)&sm->qk[i][n * HD];
        const uint4* kp = (const uint4*)&sm->qk[j][Hn + n * HD];
        float d = 0.f;
#pragma unroll
        for (int dd = 0; dd < HD / 8; dd++) {
            uint4 a = qp[dd];
            uint4 bb = kp[dd];
            const __half2* pa = (const __half2*)&a;
            const __half2* pb = (const __half2*)&bb;
#pragma unroll
            for (int jj = 0; jj < 4; jj++) {
                float2 fa = __half22float2(pa[jj]);
                float2 fb = __half22float2(pb[jj]);
                d += fa.x * fb.x + fa.y * fb.y;
            }
        }
        sm->sc[n][i][j] = d * 0.125f + sm->smask[i] * sm->smask[j];
    }
    __syncthreads();

    if (tid < NH * Kn) {
        int n = tid / Kn, i = tid % Kn;
        float* row = sm->sc[n][i];
        float mx = row[0];
#pragma unroll
        for (int j = 1; j < Kn; j++) mx = fmaxf(mx, row[j]);
        float e[Kn];
        float s = 0.f;
#pragma unroll
        for (int j = 0; j < Kn; j++) { e[j] = __expf(row[j] - mx); s += e[j]; }
        float inv = 1.f / s;
#pragma unroll
        for (int j = 0; j < Kn; j++) row[j] = e[j] * inv;
    }
    __syncthreads();

    if (tid < Kn * Kn) {
        int i = tid / Kn, j = tid % Kn;
        float s = 0.f;
#pragma unroll
        for (int n = 0; n < NH; n++) s += sm->sc[n][i][j];
        sm->wm[i][j] = s * (1.f / NH);
    }
    __syncthreads();

    if (tid < Kn) {
        int j = tid;
        float c = 0.f;
#pragma unroll
        for (int i = 0; i < Kn; i++)
            c += sm->smask[i] * sm->smask[j] * sm->wm[i][j];
        sm->contrib[j] = c;
    }
    __syncthreads();
    if (tid == 0) {
        float s = 0.f;
#pragma unroll
        for (int j = 0; j < Kn; j++) s += sm->contrib[j];
        sm->sinv = 1.f / (s + 1e-8f);
    }
    __syncthreads();

    float c[Kn];
    float inv = sm->sinv;
#pragma unroll
    for (int kk = 0; kk < Kn; kk++) c[kk] = sm->contrib[kk] * inv;

    const float4* rows[Kn];
#pragma unroll
    for (int kk = 0; kk < Kn; kk++)
        rows[kk] = (const float4*)(TE + ((size_t)b * Sn + sm->sidx[kk]) * Hn);

    float4* orow = (float4*)(out + ((size_t)b * Sn + sm->sidx[0]) * Hn);
    {
        float4 a = make_float4(0.f, 0.f, 0.f, 0.f);
#pragma unroll
        for (int kk = 0; kk < Kn; kk++) {
            float4 v = rows[kk][tid];
            a.x += c[kk] * v.x;
            a.y += c[kk] * v.y;
            a.z += c[kk] * v.z;
            a.w += c[kk] * v.w;
        }
        orow[tid] = a;
    }
}

// ---------------------------------------------------------------------------
extern "C" void kernel_launch(void* const* d_in, const int* in_sizes, int n_in,
                              void* d_out, int out_size)
{
    const float* TE   = (const float*)d_in[0];   // (32,1024,1024) f32
    const float* Wt   = (const float*)d_in[1];   // (3072,1024) f32
    const float* bias = (const float*)d_in[2];   // (3072,) f32
    const int* idx    = (const int*)d_in[3];     // (32,128,6) i32
    float* out = (float*)d_out;

    // Kernel B': copy+zero AND TE->fp16 conversion (produces g_TEh)
    {
        size_t total4 = (size_t)Bn * Sn * Hn / 4;   // 8388608
        copy_zero_conv_kernel<<<(unsigned)(total4 / 256), 256>>>(TE, idx, out);
    }

    // Kernel W: W[0:2048] -> fp16 (produces g_Wh)
    {
        size_t total4 = (size_t)NCOLS * Hn / 4;     // 524288
        conv_w_kernel<<<(unsigned)(total4 / 256), 256>>>(Wt);
    }

    // Kernel A: fp16 tensor-core projection GEMM into g_qkh
    {
        static bool attr_set = false;
        if (!attr_set) {
            cudaFuncSetAttribute(gemm_qk_f16,
                                 cudaFuncAttributeMaxDynamicSharedMemorySize,
                                 GEMM_SMEM);
            attr_set = true;
        }
        dim3 grid(NCOLS / 128, MROWS / 128);   // (16, 192)
        gemm_qk_f16<<<grid, 256, GEMM_SMEM>>>(bias, idx);
    }

    // Kernel C: attention + unified scatter (needs out + g_qkh)
    {
        static bool attr_set2 = false;
        if (!attr_set2) {
            cudaFuncSetAttribute(attn_merge_kernel,
                                 cudaFuncAttributeMaxDynamicSharedMemorySize,
                                 (int)sizeof(SmemB));
            attr_set2 = true;
        }
        attn_merge_kernel<<<Bn * Wn, 256, sizeof(SmemB)>>>(TE, idx, out);
    }
}

// round 14
// speedup vs baseline: 2.5324x; 1.1913x over previous
#include <cuda_runtime.h>
#include <cuda_fp16.h>
#include <cstdint>

// Problem constants (fixed shapes)
#define Bn 32
#define Sn 1024
#define Hn 1024
#define Wn 128
#define Kn 6
#define NH 16
#define HD 64
#define MROWS (Bn * Wn * Kn)   // 24576
#define NCOLS (2 * Hn)         // 2048
#define NWIN (Bn * Wn)         // 4096

// Scratch: qk projection output (fp16, compacted rows), fp16 TE/W copies,
// compaction tables.
__device__ __half g_qkh[(size_t)MROWS * NCOLS];   // 100 MB
__device__ __half g_TEh[(size_t)Bn * Sn * Hn];    // 64 MB
__device__ __half g_Wh[(size_t)NCOLS * Hn];       // 4 MB
__device__ int g_winStart[NWIN + 1];
__device__ long long g_srcOff2[MROWS];
__device__ __half g_biasH[NCOLS];

__device__ __forceinline__ uint32_t smem_u32(const void* p) {
    uint32_t a;
    asm("{ .reg .u64 t; cvta.to.shared.u64 t, %1; cvt.u32.u64 %0, t; }" : "=r"(a) : "l"(p));
    return a;
}
__device__ __forceinline__ void mma_f16(float& c0, float& c1, float& c2, float& c3,
                                        uint32_t a0, uint32_t a1, uint32_t a2, uint32_t a3,
                                        uint32_t b0, uint32_t b1)
{
    asm volatile(
        "mma.sync.aligned.m16n8k16.row.col.f32.f16.f16.f32 "
        "{%0,%1,%2,%3},{%4,%5,%6,%7},{%8,%9},{%0,%1,%2,%3};"
        : "+f"(c0), "+f"(c1), "+f"(c2), "+f"(c3)
        : "r"(a0), "r"(a1), "r"(a2), "r"(a3), "r"(b0), "r"(b1));
}
__device__ __forceinline__ void ldsm4(uint32_t& r0, uint32_t& r1, uint32_t& r2, uint32_t& r3,
                                      uint32_t addr)
{
    asm volatile("ldmatrix.sync.aligned.m8n8.x4.shared.b16 {%0,%1,%2,%3}, [%4];"
                 : "=r"(r0), "=r"(r1), "=r"(r2), "=r"(r3) : "r"(addr));
}
__device__ __forceinline__ void cpasync16(uint32_t dst, const void* src, uint32_t sz) {
    asm volatile("cp.async.cg.shared.global [%0], [%1], 16, %2;"
                 :: "r"(dst), "l"(src), "r"(sz) : "memory");
}
#define CP_COMMIT() asm volatile("cp.async.commit_group;" ::: "memory")
#define CP_WAIT(n)  asm volatile("cp.async.wait_group %0;" :: "n"(n) : "memory")
#define SW128(o) ((o) ^ (((o) >> 3) & 0x70))

// ---------------------------------------------------------------------------
// Kernel P: per-window active-length scan + compact gather table + bias->fp16.
// Active slots are a contiguous prefix (mask = k < lengths), slot0 always on.
// One block, 1024 threads, deterministic Hillis-Steele scan.
// ---------------------------------------------------------------------------
__global__ __launch_bounds__(1024) void scan_kernel(
    const int* __restrict__ idx, const float* __restrict__ bias)
{
    __shared__ int part[1024];
    const int t = threadIdx.x;

    int myLen[4];
    int s = 0;
#pragma unroll
    for (int j = 0; j < 4; j++) {
        int w = t * 4 + j;
        int len = 1;                       // k=0 always active
#pragma unroll
        for (int k = 1; k < Kn; k++) len += (idx[w * Kn + k] != 0) ? 1 : 0;
        myLen[j] = len;
        s += len;
    }
    part[t] = s;
    __syncthreads();
    for (int off = 1; off < 1024; off <<= 1) {
        int v = (t >= off) ? part[t - off] : 0;
        __syncthreads();
        part[t] += v;
        __syncthreads();
    }
    int base = part[t] - s;                // exclusive prefix
#pragma unroll
    for (int j = 0; j < 4; j++) {
        int w = t * 4 + j;
        g_winStart[w] = base;
        int b = w >> 7;
        for (int k = 0; k < myLen[j]; k++) {
            int iv = idx[w * Kn + k];
            g_srcOff2[base + k] = (long long)(b * Sn + iv) * Hn;
        }
        base += myLen[j];
    }
    if (t == 1023) g_winStart[NWIN] = part[1023];

    for (int i = t; i < NCOLS; i += 1024) g_biasH[i] = __float2half(bias[i]);
}

// ---------------------------------------------------------------------------
// Kernel A: compacted FP16 tensor-core GEMM, cp.async in + ldmatrix out.
//   qkh[c][n] = sum_h TEh[srcOff2[c] + h] * Wh[n][h] + bias[n],  c < activeM
// Tile 128x128, BK=32 (fp16, 64B rows), 6 stages, 32 iters, 256 threads
// (8 warps 4x2), warp tile 32x64 via mma.m16n8k16. Output fp16.
// Blocks whose row range is entirely >= activeM exit immediately.
// ---------------------------------------------------------------------------
#define STAGE_BYTES 16384
#define NSTAGE 6
#define GEMM_SMEM (2048 + NSTAGE * STAGE_BYTES)

__global__ __launch_bounds__(256, 2) void gemm_qk_f16(
    const float* __restrict__ bias)
{
    const int activeM = g_winStart[NWIN];
    const int rowBase = blockIdx.y * 128;
    if (rowBase >= activeM) return;

    extern __shared__ unsigned char sm[];
    long long* srcOff = (long long*)sm;
    float* biasSm = (float*)(sm + 1024);
    const uint32_t smBase = smem_u32(sm);

    const int tid = threadIdx.x;
    const int colBase = blockIdx.x * 128;

    if (tid < 128) {
        int c = rowBase + tid;
        srcOff[tid] = (c < activeM) ? g_srcOff2[c] : -1LL;
        biasSm[tid] = bias[colBase + tid];
    }
    __syncthreads();

    // ---- loader mapping: thread t -> row t>>1, 32B half-row t&1 ----
    const int lrow = tid >> 1;
    const int lhalf = tid & 1;
    const long long aOff = srcOff[lrow];
    const __half* aSrc = g_TEh + (aOff >= 0 ? aOff : 0) + lhalf * 16;   // halves
    const uint32_t aSz = (aOff >= 0) ? 16u : 0u;
    const __half* bSrc = g_Wh + (size_t)(colBase + lrow) * Hn + lhalf * 16;

    const uint32_t dOff = (uint32_t)(lrow * 64 + lhalf * 32);
    const uint32_t aD0 = smBase + 2048 + SW128(dOff);
    const uint32_t aD1 = smBase + 2048 + SW128(dOff + 16);
    const uint32_t bD0 = aD0 + 8192;
    const uint32_t bD1 = aD1 + 8192;

    // ---- compute mapping ----
    const int wid = tid >> 5, lane = tid & 31;
    const int wr = wid >> 1, wc = wid & 1;            // 4 x 2 warp grid
    const int g4 = lane >> 2, t4 = lane & 3;

    uint32_t aLd[2];
    {
        const int rowsel = (lane & 7) + ((lane >> 3) & 1) * 8;
        const uint32_t colHalf = (uint32_t)((lane >> 4) & 1) * 16u;
#pragma unroll
        for (int mi = 0; mi < 2; mi++) {
            uint32_t o = (uint32_t)((wr * 32 + mi * 16 + rowsel) * 64) + colHalf;
            aLd[mi] = smBase + 2048 + SW128(o);
        }
    }
    uint32_t bLd[4];
    {
        const int rowsel = (lane & 7) + ((lane >> 4) & 1) * 8;
        const uint32_t colHalf = (uint32_t)((lane >> 3) & 1) * 16u;
#pragma unroll
        for (int p = 0; p < 4; p++) {
            uint32_t o = (uint32_t)((wc * 64 + p * 16 + rowsel) * 64) + colHalf;
            bLd[p] = smBase + 2048 + 8192 + SW128(o);
        }
    }

    float acc[2][8][4];
#pragma unroll
    for (int mi = 0; mi < 2; mi++)
#pragma unroll
        for (int ni = 0; ni < 8; ni++)
#pragma unroll
            for (int q = 0; q < 4; q++) acc[mi][ni][q] = 0.f;

    // ---- prologue: prefetch stages 0..4 ----
#pragma unroll
    for (int s = 0; s < NSTAGE - 1; s++) {
        const uint32_t sb = (uint32_t)(s * STAGE_BYTES);
        const int k0 = s * 32;                         // halves
        cpasync16(aD0 + sb, aSrc + k0, aSz);
        cpasync16(aD1 + sb, aSrc + k0 + 8, aSz);
        cpasync16(bD0 + sb, bSrc + k0, 16u);
        cpasync16(bD1 + sb, bSrc + k0 + 8, 16u);
        CP_COMMIT();
    }

    // ---- mainloop: 32 iterations of BK=32 (fp16) ----
    for (int it = 0; it < 32; ++it) {
        CP_WAIT(4);
        __syncthreads();

        if (it + NSTAGE - 1 < 32) {
            const uint32_t sb = (uint32_t)(((it + NSTAGE - 1) % NSTAGE) * STAGE_BYTES);
            const int k0 = (it + NSTAGE - 1) * 32;
            cpasync16(aD0 + sb, aSrc + k0, aSz);
            cpasync16(aD1 + sb, aSrc + k0 + 8, aSz);
            cpasync16(bD0 + sb, bSrc + k0, 16u);
            cpasync16(bD1 + sb, bSrc + k0 + 8, 16u);
        }
        CP_COMMIT();

        const uint32_t sb = (uint32_t)((it % NSTAGE) * STAGE_BYTES);
#pragma unroll
        for (int ks = 0; ks < 2; ks++) {
            const uint32_t kx = (uint32_t)(ks * 32);
            uint32_t af[2][4];
#pragma unroll
            for (int mi = 0; mi < 2; mi++)
                ldsm4(af[mi][0], af[mi][1], af[mi][2], af[mi][3],
                      (aLd[mi] + sb) ^ kx);

            uint32_t bf[4][4];
#pragma unroll
            for (int p = 0; p < 4; p++)
                ldsm4(bf[p][0], bf[p][1], bf[p][2], bf[p][3],
                      (bLd[p] + sb) ^ kx);

#pragma unroll
            for (int p = 0; p < 4; p++)
#pragma unroll
                for (int h = 0; h < 2; h++) {
                    const int ni = 2 * p + h;
#pragma unroll
                    for (int mi = 0; mi < 2; mi++)
                        mma_f16(acc[mi][ni][0], acc[mi][ni][1], acc[mi][ni][2], acc[mi][ni][3],
                                af[mi][0], af[mi][1], af[mi][2], af[mi][3],
                                bf[p][2 * h], bf[p][2 * h + 1]);
                }
        }
    }

    // ---- epilogue: add bias, convert to fp16, store to g_qkh ----
#pragma unroll
    for (int mi = 0; mi < 2; mi++) {
        int row0 = rowBase + wr * 32 + mi * 16 + g4;
#pragma unroll
        for (int ni = 0; ni < 8; ni++) {
            int cl = wc * 64 + ni * 8 + t4 * 2;
            float b0 = biasSm[cl], b1 = biasSm[cl + 1];
            __half2 v0 = __floats2half2_rn(acc[mi][ni][0] + b0, acc[mi][ni][1] + b1);
            __half2 v1 = __floats2half2_rn(acc[mi][ni][2] + b0, acc[mi][ni][3] + b1);
            *(__half2*)&g_qkh[(size_t)row0 * NCOLS + colBase + cl] = v0;
            *(__half2*)&g_qkh[(size_t)(row0 + 8) * NCOLS + colBase + cl] = v1;
        }
    }
}

// ---------------------------------------------------------------------------
// Kernel B': copy TE -> out (zeroing masked subtoken rows) AND convert TE->fp16.
// ---------------------------------------------------------------------------
__global__ __launch_bounds__(256) void copy_zero_conv_kernel(
    const float* __restrict__ TE,
    const int* __restrict__ idx,
    float* __restrict__ out)
{
    size_t gid = (size_t)blockIdx.x * 256 + threadIdx.x;  // float4 index
    float4 v = ((const float4*)TE)[gid];

    __half2 h0 = __floats2half2_rn(v.x, v.y);
    __half2 h1 = __floats2half2_rn(v.z, v.w);
    uint2 hv;
    hv.x = *(uint32_t*)&h0;
    hv.y = *(uint32_t*)&h1;
    *(uint2*)(g_TEh + gid * 4) = hv;

    int row = (int)(gid >> 8);        // H/4 = 256 float4 per row
    int b = row >> 10;                // / S
    int s = row & 1023;
    int w = s >> 3;
    int kk = s & 7;
    bool zero = false;
    if (kk < Kn) {
        int iv = idx[(b * Wn + w) * Kn + kk];
        zero = (kk == 0) || (iv != 0);
    }
    if (zero) v = make_float4(0.f, 0.f, 0.f, 0.f);
    ((float4*)out)[gid] = v;
}

// ---------------------------------------------------------------------------
// Kernel W: convert W[0:2048] rows to fp16.
// ---------------------------------------------------------------------------
__global__ __launch_bounds__(256) void conv_w_kernel(const float* __restrict__ Wt)
{
    size_t gid = (size_t)blockIdx.x * 256 + threadIdx.x;
    float4 v = ((const float4*)Wt)[gid];
    __half2 h0 = __floats2half2_rn(v.x, v.y);
    __half2 h1 = __floats2half2_rn(v.z, v.w);
    uint2 hv;
    hv.x = *(uint32_t*)&h0;
    hv.y = *(uint32_t*)&h1;
    *(uint2*)(g_Wh + gid * 4) = hv;
}

// ---------------------------------------------------------------------------
// Kernel C: per-window attention -> contrib -> unified, scatter to out.
// qk rows come from the compacted g_qkh (r < len) or the bias vector (masked).
// fp16 smem rows padded +16 halves to avoid bank-conflict row stride.
// ---------------------------------------------------------------------------
#define QKSTRIDE_H (NCOLS + 16)   // 2064 halves = 4128 B per row

struct SmemB {
    __half qk[Kn][QKSTRIDE_H];    // ~24.2 KB
    float sc[NH][Kn][Kn];
    float wm[Kn][Kn];
    float contrib[8];
    float smask[8];
    int sidx[8];
    float sinv;
};

__global__ __launch_bounds__(256) void attn_merge_kernel(
    const float* __restrict__ TE,
    const int* __restrict__ idx,
    float* __restrict__ out)
{
    extern __shared__ unsigned char smraw[];
    SmemB* sm = reinterpret_cast<SmemB*>(smraw);

    const int tid = threadIdx.x;
    const int wg = blockIdx.x;     // window id = b*W + w
    const int b = wg >> 7;

    const int start = g_winStart[wg];
    const int len = g_winStart[wg + 1] - start;

    if (tid < Kn) {
        sm->sidx[tid] = idx[wg * Kn + tid];
        sm->smask[tid] = (tid < len) ? 1.f : 0.f;
    }

    // Load 6 qk rows: compacted GEMM output for r<len, bias vector otherwise.
#pragma unroll
    for (int r = 0; r < Kn; r++) {
        const __half* srcR = (r < len) ? (g_qkh + (size_t)(start + r) * NCOLS)
                                       : g_biasH;
        ((uint4*)&sm->qk[r][0])[tid] = ((const uint4*)srcR)[tid];
    }
    __syncthreads();

    // Scores: 16 heads x 6 x 6 = 576 dot(64) tasks (fp16 operands, f32 accum)
    for (int t = tid; t < NH * Kn * Kn; t += 256) {
        int n = t / (Kn * Kn);
        int ij = t % (Kn * Kn);
        int i = ij / Kn, j = ij % Kn;
        const uint4* qp = (const uint4*)&sm->qk[i][n * HD];
        const uint4* kp = (const uint4*)&sm->qk[j][Hn + n * HD];
        float d = 0.f;
#pragma unroll
        for (int dd = 0; dd < HD / 8; dd++) {
            uint4 a = qp[dd];
            uint4 bb = kp[dd];
            const __half2* pa = (const __half2*)&a;
            const __half2* pb = (const __half2*)&bb;
#pragma unroll
            for (int jj = 0; jj < 4; jj++) {
                float2 fa = __half22float2(pa[jj]);
                float2 fb = __half22float2(pb[jj]);
                d += fa.x * fb.x + fa.y * fb.y;
            }
        }
        sm->sc[n][i][j] = d * 0.125f + sm->smask[i] * sm->smask[j];
    }
    __syncthreads();

    if (tid < NH * Kn) {
        int n = tid / Kn, i = tid % Kn;
        float* row = sm->sc[n][i];
        float mx = row[0];
#pragma unroll
        for (int j = 1; j < Kn; j++) mx = fmaxf(mx, row[j]);
        float e[Kn];
        float s = 0.f;
#pragma unroll
        for (int j = 0; j < Kn; j++) { e[j] = __expf(row[j] - mx); s += e[j]; }
        float inv = 1.f / s;
#pragma unroll
        for (int j = 0; j < Kn; j++) row[j] = e[j] * inv;
    }
    __syncthreads();

    if (tid < Kn * Kn) {
        int i = tid / Kn, j = tid % Kn;
        float s = 0.f;
#pragma unroll
        for (int n = 0; n < NH; n++) s += sm->sc[n][i][j];
        sm->wm[i][j] = s * (1.f / NH);
    }
    __syncthreads();

    if (tid < Kn) {
        int j = tid;
        float c = 0.f;
#pragma unroll
        for (int i = 0; i < Kn; i++)
            c += sm->smask[i] * sm->smask[j] * sm->wm[i][j];
        sm->contrib[j] = c;
    }
    __syncthreads();
    if (tid == 0) {
        float s = 0.f;
#pragma unroll
        for (int j = 0; j < Kn; j++) s += sm->contrib[j];
        sm->sinv = 1.f / (s + 1e-8f);
    }
    __syncthreads();

    float c[Kn];
    float inv = sm->sinv;
#pragma unroll
    for (int kk = 0; kk < Kn; kk++) c[kk] = sm->contrib[kk] * inv;

    const float4* rows[Kn];
#pragma unroll
    for (int kk = 0; kk < Kn; kk++)
        rows[kk] = (const float4*)(TE + ((size_t)b * Sn + sm->sidx[kk]) * Hn);

    float4* orow = (float4*)(out + ((size_t)b * Sn + sm->sidx[0]) * Hn);
    {
        float4 a = make_float4(0.f, 0.f, 0.f, 0.f);
#pragma unroll
        for (int kk = 0; kk < Kn; kk++) {
            float4 v = rows[kk][tid];
            a.x += c[kk] * v.x;
            a.y += c[kk] * v.y;
            a.z += c[kk] * v.z;
            a.w += c[kk] * v.w;
        }
        orow[tid] = a;
    }
}

// ---------------------------------------------------------------------------
extern "C" void kernel_launch(void* const* d_in, const int* in_sizes, int n_in,
                              void* d_out, int out_size)
{
    const float* TE   = (const float*)d_in[0];   // (32,1024,1024) f32
    const float* Wt   = (const float*)d_in[1];   // (3072,1024) f32
    const float* bias = (const float*)d_in[2];   // (3072,) f32
    const int* idx    = (const int*)d_in[3];     // (32,128,6) i32
    float* out = (float*)d_out;

    // Kernel P: window scan + compact gather table + bias fp16
    scan_kernel<<<1, 1024>>>(idx, bias);

    // Kernel B': copy+zero AND TE->fp16 conversion (produces g_TEh)
    {
        size_t total4 = (size_t)Bn * Sn * Hn / 4;   // 8388608
        copy_zero_conv_kernel<<<(unsigned)(total4 / 256), 256>>>(TE, idx, out);
    }

    // Kernel W: W[0:2048] -> fp16 (produces g_Wh)
    {
        size_t total4 = (size_t)NCOLS * Hn / 4;     // 524288
        conv_w_kernel<<<(unsigned)(total4 / 256), 256>>>(Wt);
    }

    // Kernel A: compacted fp16 tensor-core projection GEMM into g_qkh
    {
        static bool attr_set = false;
        if (!attr_set) {
            cudaFuncSetAttribute(gemm_qk_f16,
                                 cudaFuncAttributeMaxDynamicSharedMemorySize,
                                 GEMM_SMEM);
            attr_set = true;
        }
        dim3 grid(NCOLS / 128, MROWS / 128);   // (16, 192); tail blocks exit
        gemm_qk_f16<<<grid, 256, GEMM_SMEM>>>(bias);
    }

    // Kernel C: attention + unified scatter (needs out + g_qkh + winStart)
    {
        static bool attr_set2 = false;
        if (!attr_set2) {
            cudaFuncSetAttribute(attn_merge_kernel,
                                 cudaFuncAttributeMaxDynamicSharedMemorySize,
                                 (int)sizeof(SmemB));
            attr_set2 = true;
        }
        attn_merge_kernel<<<NWIN, 256, sizeof(SmemB)>>>(TE, idx, out);
    }
}

// round 15
// speedup vs baseline: 2.5667x; 1.0135x over previous
#include <cuda_runtime.h>
#include <cuda_fp16.h>
#include <cstdint>

// Problem constants (fixed shapes)
#define Bn 32
#define Sn 1024
#define Hn 1024
#define Wn 128
#define Kn 6
#define NH 16
#define HD 64
#define MROWS (Bn * Wn * Kn)   // 24576
#define NCOLS (2 * Hn)         // 2048
#define NWIN (Bn * Wn)         // 4096

// Scratch: qk projection output (fp16, compacted rows), fp16 TE/W copies,
// compaction tables.
__device__ __half g_qkh[(size_t)MROWS * NCOLS];   // 100 MB
__device__ __half g_TEh[(size_t)Bn * Sn * Hn];    // 64 MB
__device__ __half g_Wh[(size_t)NCOLS * Hn];       // 4 MB
__device__ int g_winStart[NWIN + 1];
__device__ long long g_srcOff2[MROWS];
__device__ __half g_biasH[NCOLS];

__device__ __forceinline__ uint32_t smem_u32(const void* p) {
    uint32_t a;
    asm("{ .reg .u64 t; cvta.to.shared.u64 t, %1; cvt.u32.u64 %0, t; }" : "=r"(a) : "l"(p));
    return a;
}
__device__ __forceinline__ void mma_f16(float& c0, float& c1, float& c2, float& c3,
                                        uint32_t a0, uint32_t a1, uint32_t a2, uint32_t a3,
                                        uint32_t b0, uint32_t b1)
{
    asm volatile(
        "mma.sync.aligned.m16n8k16.row.col.f32.f16.f16.f32 "
        "{%0,%1,%2,%3},{%4,%5,%6,%7},{%8,%9},{%0,%1,%2,%3};"
        : "+f"(c0), "+f"(c1), "+f"(c2), "+f"(c3)
        : "r"(a0), "r"(a1), "r"(a2), "r"(a3), "r"(b0), "r"(b1));
}
__device__ __forceinline__ void ldsm4(uint32_t& r0, uint32_t& r1, uint32_t& r2, uint32_t& r3,
                                      uint32_t addr)
{
    asm volatile("ldmatrix.sync.aligned.m8n8.x4.shared.b16 {%0,%1,%2,%3}, [%4];"
                 : "=r"(r0), "=r"(r1), "=r"(r2), "=r"(r3) : "r"(addr));
}
__device__ __forceinline__ void cpasync16(uint32_t dst, const void* src, uint32_t sz) {
    asm volatile("cp.async.cg.shared.global [%0], [%1], 16, %2;"
                 :: "r"(dst), "l"(src), "r"(sz) : "memory");
}
#define CP_COMMIT() asm volatile("cp.async.commit_group;" ::: "memory")
#define CP_WAIT(n)  asm volatile("cp.async.wait_group %0;" :: "n"(n) : "memory")
#define SW128(o) ((o) ^ (((o) >> 3) & 0x70))

// ---------------------------------------------------------------------------
// Kernel P: per-window active-length scan + compact gather table + bias->fp16.
// ---------------------------------------------------------------------------
__global__ __launch_bounds__(1024) void scan_kernel(
    const int* __restrict__ idx, const float* __restrict__ bias)
{
    __shared__ int part[1024];
    const int t = threadIdx.x;

    int myLen[4];
    int s = 0;
#pragma unroll
    for (int j = 0; j < 4; j++) {
        int w = t * 4 + j;
        int len = 1;                       // k=0 always active
#pragma unroll
        for (int k = 1; k < Kn; k++) len += (idx[w * Kn + k] != 0) ? 1 : 0;
        myLen[j] = len;
        s += len;
    }
    part[t] = s;
    __syncthreads();
    for (int off = 1; off < 1024; off <<= 1) {
        int v = (t >= off) ? part[t - off] : 0;
        __syncthreads();
        part[t] += v;
        __syncthreads();
    }
    int base = part[t] - s;                // exclusive prefix
#pragma unroll
    for (int j = 0; j < 4; j++) {
        int w = t * 4 + j;
        g_winStart[w] = base;
        int b = w >> 7;
        for (int k = 0; k < myLen[j]; k++) {
            int iv = idx[w * Kn + k];
            g_srcOff2[base + k] = (long long)(b * Sn + iv) * Hn;
        }
        base += myLen[j];
    }
    if (t == 1023) g_winStart[NWIN] = part[1023];

    for (int i = t; i < NCOLS; i += 1024) g_biasH[i] = __float2half(bias[i]);
}

// ---------------------------------------------------------------------------
// Kernel A: compacted FP16 tensor-core GEMM, cp.async in + ldmatrix out.
// Tile 128x256, BK=32, 4 stages of 24KB (A 8KB | B 16KB), 32 iters,
// 512 threads (16 warps, 4m x 4n), warp tile 32x64 via mma.m16n8k16.
// 48 B of operand traffic per HMMA (vs 64 at 128x128) -> compute-bound.
// ---------------------------------------------------------------------------
#define STAGE_BYTES 24576
#define NSTAGE 4
#define GEMM_SMEM (2048 + NSTAGE * STAGE_BYTES)

__global__ __launch_bounds__(512, 1) void gemm_qk_f16(
    const float* __restrict__ bias)
{
    const int activeM = g_winStart[NWIN];
    const int rowBase = blockIdx.y * 128;
    if (rowBase >= activeM) return;

    extern __shared__ unsigned char sm[];
    long long* srcOff = (long long*)sm;
    float* biasSm = (float*)(sm + 1024);
    const uint32_t smBase = smem_u32(sm);

    const int tid = threadIdx.x;
    const int colBase = blockIdx.x * 256;

    if (tid < 128) {
        int c = rowBase + tid;
        srcOff[tid] = (c < activeM) ? g_srcOff2[c] : -1LL;
    }
    if (tid < 256) biasSm[tid] = bias[colBase + tid];
    __syncthreads();

    // ---- A loader: 4 threads/row, 16B each ----
    const int arow = tid >> 2;            // 0..127
    const int aq = tid & 3;               // 16B quarter of 64B row
    const long long aOff = srcOff[arow];
    const __half* aSrc = g_TEh + (aOff >= 0 ? aOff : 0) + aq * 8;   // halves
    const uint32_t aSz = (aOff >= 0) ? 16u : 0u;
    const uint32_t aDst = smBase + 2048 + SW128((uint32_t)(arow * 64 + aq * 16));

    // ---- B loader: 2 threads/row, 32B each (two 16B cp.async) ----
    const int brow = tid >> 1;            // 0..255
    const int bh = tid & 1;
    const __half* bSrc = g_Wh + (size_t)(colBase + brow) * Hn + bh * 16;
    const uint32_t bDst0 = smBase + 2048 + 8192 + SW128((uint32_t)(brow * 64 + bh * 32));
    const uint32_t bDst1 = smBase + 2048 + 8192 + SW128((uint32_t)(brow * 64 + bh * 32 + 16));

    // ---- compute mapping: 16 warps = 4(m) x 4(n) ----
    const int wid = tid >> 5, lane = tid & 31;
    const int wr = wid >> 2, wc = wid & 3;
    const int g4 = lane >> 2, t4 = lane & 3;

    uint32_t aLd[2];
    {
        const int rowsel = (lane & 7) + ((lane >> 3) & 1) * 8;
        const uint32_t colHalf = (uint32_t)((lane >> 4) & 1) * 16u;
#pragma unroll
        for (int mi = 0; mi < 2; mi++) {
            uint32_t o = (uint32_t)((wr * 32 + mi * 16 + rowsel) * 64) + colHalf;
            aLd[mi] = smBase + 2048 + SW128(o);
        }
    }
    uint32_t bLd[4];
    {
        const int rowsel = (lane & 7) + ((lane >> 4) & 1) * 8;
        const uint32_t colHalf = (uint32_t)((lane >> 3) & 1) * 16u;
#pragma unroll
        for (int p = 0; p < 4; p++) {
            uint32_t o = (uint32_t)((wc * 64 + p * 16 + rowsel) * 64) + colHalf;
            bLd[p] = smBase + 2048 + 8192 + SW128(o);
        }
    }

    float acc[2][8][4];
#pragma unroll
    for (int mi = 0; mi < 2; mi++)
#pragma unroll
        for (int ni = 0; ni < 8; ni++)
#pragma unroll
            for (int q = 0; q < 4; q++) acc[mi][ni][q] = 0.f;

    // ---- prologue: prefetch stages 0..2 ----
#pragma unroll
    for (int s = 0; s < NSTAGE - 1; s++) {
        const uint32_t sb = (uint32_t)(s * STAGE_BYTES);
        const int k0 = s * 32;                         // halves
        cpasync16(aDst + sb, aSrc + k0, aSz);
        cpasync16(bDst0 + sb, bSrc + k0, 16u);
        cpasync16(bDst1 + sb, bSrc + k0 + 8, 16u);
        CP_COMMIT();
    }

    // ---- mainloop: 32 iterations of BK=32 (fp16) ----
    for (int it = 0; it < 32; ++it) {
        CP_WAIT(2);
        __syncthreads();

        if (it + NSTAGE - 1 < 32) {
            const uint32_t sb = (uint32_t)(((it + NSTAGE - 1) % NSTAGE) * STAGE_BYTES);
            const int k0 = (it + NSTAGE - 1) * 32;
            cpasync16(aDst + sb, aSrc + k0, aSz);
            cpasync16(bDst0 + sb, bSrc + k0, 16u);
            cpasync16(bDst1 + sb, bSrc + k0 + 8, 16u);
        }
        CP_COMMIT();

        const uint32_t sb = (uint32_t)((it % NSTAGE) * STAGE_BYTES);
#pragma unroll
        for (int ks = 0; ks < 2; ks++) {
            const uint32_t kx = (uint32_t)(ks * 32);
            uint32_t af[2][4];
#pragma unroll
            for (int mi = 0; mi < 2; mi++)
                ldsm4(af[mi][0], af[mi][1], af[mi][2], af[mi][3],
                      (aLd[mi] + sb) ^ kx);

            uint32_t bf[4][4];
#pragma unroll
            for (int p = 0; p < 4; p++)
                ldsm4(bf[p][0], bf[p][1], bf[p][2], bf[p][3],
                      (bLd[p] + sb) ^ kx);

#pragma unroll
            for (int p = 0; p < 4; p++)
#pragma unroll
                for (int h = 0; h < 2; h++) {
                    const int ni = 2 * p + h;
#pragma unroll
                    for (int mi = 0; mi < 2; mi++)
                        mma_f16(acc[mi][ni][0], acc[mi][ni][1], acc[mi][ni][2], acc[mi][ni][3],
                                af[mi][0], af[mi][1], af[mi][2], af[mi][3],
                                bf[p][2 * h], bf[p][2 * h + 1]);
                }
        }
    }

    // ---- epilogue: add bias, convert to fp16, store to g_qkh ----
#pragma unroll
    for (int mi = 0; mi < 2; mi++) {
        int row0 = rowBase + wr * 32 + mi * 16 + g4;
#pragma unroll
        for (int ni = 0; ni < 8; ni++) {
            int cl = wc * 64 + ni * 8 + t4 * 2;
            float b0 = biasSm[cl], b1 = biasSm[cl + 1];
            __half2 v0 = __floats2half2_rn(acc[mi][ni][0] + b0, acc[mi][ni][1] + b1);
            __half2 v1 = __floats2half2_rn(acc[mi][ni][2] + b0, acc[mi][ni][3] + b1);
            *(__half2*)&g_qkh[(size_t)row0 * NCOLS + colBase + cl] = v0;
            *(__half2*)&g_qkh[(size_t)(row0 + 8) * NCOLS + colBase + cl] = v1;
        }
    }
}

// ---------------------------------------------------------------------------
// Kernel B': copy TE -> out (zeroing masked subtoken rows) AND convert TE->fp16.
// ---------------------------------------------------------------------------
__global__ __launch_bounds__(256) void copy_zero_conv_kernel(
    const float* __restrict__ TE,
    const int* __restrict__ idx,
    float* __restrict__ out)
{
    size_t gid = (size_t)blockIdx.x * 256 + threadIdx.x;  // float4 index
    float4 v = ((const float4*)TE)[gid];

    __half2 h0 = __floats2half2_rn(v.x, v.y);
    __half2 h1 = __floats2half2_rn(v.z, v.w);
    uint2 hv;
    hv.x = *(uint32_t*)&h0;
    hv.y = *(uint32_t*)&h1;
    *(uint2*)(g_TEh + gid * 4) = hv;

    int row = (int)(gid >> 8);        // H/4 = 256 float4 per row
    int b = row >> 10;                // / S
    int s = row & 1023;
    int w = s >> 3;
    int kk = s & 7;
    bool zero = false;
    if (kk < Kn) {
        int iv = idx[(b * Wn + w) * Kn + kk];
        zero = (kk == 0) || (iv != 0);
    }
    if (zero) v = make_float4(0.f, 0.f, 0.f, 0.f);
    ((float4*)out)[gid] = v;
}

// ---------------------------------------------------------------------------
// Kernel W: convert W[0:2048] rows to fp16.
// ---------------------------------------------------------------------------
__global__ __launch_bounds__(256) void conv_w_kernel(const float* __restrict__ Wt)
{
    size_t gid = (size_t)blockIdx.x * 256 + threadIdx.x;
    float4 v = ((const float4*)Wt)[gid];
    __half2 h0 = __floats2half2_rn(v.x, v.y);
    __half2 h1 = __floats2half2_rn(v.z, v.w);
    uint2 hv;
    hv.x = *(uint32_t*)&h0;
    hv.y = *(uint32_t*)&h1;
    *(uint2*)(g_Wh + gid * 4) = hv;
}

// ---------------------------------------------------------------------------
// Kernel C: per-window attention -> contrib -> unified, scatter to out.
// ---------------------------------------------------------------------------
#define QKSTRIDE_H (NCOLS + 16)   // 2064 halves = 4128 B per row

struct SmemB {
    __half qk[Kn][QKSTRIDE_H];    // ~24.2 KB
    float sc[NH][Kn][Kn];
    float wm[Kn][Kn];
    float contrib[8];
    float smask[8];
    int sidx[8];
    float sinv;
};

__global__ __launch_bounds__(256) void attn_merge_kernel(
    const float* __restrict__ TE,
    const int* __restrict__ idx,
    float* __restrict__ out)
{
    extern __shared__ unsigned char smraw[];
    SmemB* sm = reinterpret_cast<SmemB*>(smraw);

    const int tid = threadIdx.x;
    const int wg = blockIdx.x;     // window id = b*W + w
    const int b = wg >> 7;

    const int start = g_winStart[wg];
    const int len = g_winStart[wg + 1] - start;

    if (tid < Kn) {
        sm->sidx[tid] = idx[wg * Kn + tid];
        sm->smask[tid] = (tid < len) ? 1.f : 0.f;
    }

#pragma unroll
    for (int r = 0; r < Kn; r++) {
        const __half* srcR = (r < len) ? (g_qkh + (size_t)(start + r) * NCOLS)
                                       : g_biasH;
        ((uint4*)&sm->qk[r][0])[tid] = ((const uint4*)srcR)[tid];
    }
    __syncthreads();

    for (int t = tid; t < NH * Kn * Kn; t += 256) {
        int n = t / (Kn * Kn);
        int ij = t % (Kn * Kn);
        int i = ij / Kn, j = ij % Kn;
        const uint4* qp = (const uint4*)&sm->qk[i][n * HD];
        const uint4* kp = (const uint4*)&sm->qk[j][Hn + n * HD];
        float d = 0.f;
#pragma unroll
        for (int dd = 0; dd < HD / 8; dd++) {
            uint4 a = qp[dd];
            uint4 bb = kp[dd];
            const __half2* pa = (const __half2*)&a;
            const __half2* pb = (const __half2*)&bb;
#pragma unroll
            for (int jj = 0; jj < 4; jj++) {
                float2 fa = __half22float2(pa[jj]);
                float2 fb = __half22float2(pb[jj]);
                d += fa.x * fb.x + fa.y * fb.y;
            }
        }
        sm->sc[n][i][j] = d * 0.125f + sm->smask[i] * sm->smask[j];
    }
    __syncthreads();

    if (tid < NH * Kn) {
        int n = tid / Kn, i = tid % Kn;
        float* row = sm->sc[n][i];
        float mx = row[0];
#pragma unroll
        for (int j = 1; j < Kn; j++) mx = fmaxf(mx, row[j]);
        float e[Kn];
        float s = 0.f;
#pragma unroll
        for (int j = 0; j < Kn; j++) { e[j] = __expf(row[j] - mx); s += e[j]; }
        float inv = 1.f / s;
#pragma unroll
        for (int j = 0; j < Kn; j++) row[j] = e[j] * inv;
    }
    __syncthreads();

    if (tid < Kn * Kn) {
        int i = tid / Kn, j = tid % Kn;
        float s = 0.f;
#pragma unroll
        for (int n = 0; n < NH; n++) s += sm->sc[n][i][j];
        sm->wm[i][j] = s * (1.f / NH);
    }
    __syncthreads();

    if (tid < Kn) {
        int j = tid;
        float c = 0.f;
#pragma unroll
        for (int i = 0; i < Kn; i++)
            c += sm->smask[i] * sm->smask[j] * sm->wm[i][j];
        sm->contrib[j] = c;
    }
    __syncthreads();
    if (tid == 0) {
        float s = 0.f;
#pragma unroll
        for (int j = 0; j < Kn; j++) s += sm->contrib[j];
        sm->sinv = 1.f / (s + 1e-8f);
    }
    __syncthreads();

    float c[Kn];
    float inv = sm->sinv;
#pragma unroll
    for (int kk = 0; kk < Kn; kk++) c[kk] = sm->contrib[kk] * inv;

    const float4* rows[Kn];
#pragma unroll
    for (int kk = 0; kk < Kn; kk++)
        rows[kk] = (const float4*)(TE + ((size_t)b * Sn + sm->sidx[kk]) * Hn);

    float4* orow = (float4*)(out + ((size_t)b * Sn + sm->sidx[0]) * Hn);
    {
        float4 a = make_float4(0.f, 0.f, 0.f, 0.f);
#pragma unroll
        for (int kk = 0; kk < Kn; kk++) {
            float4 v = rows[kk][tid];
            a.x += c[kk] * v.x;
            a.y += c[kk] * v.y;
            a.z += c[kk] * v.z;
            a.w += c[kk] * v.w;
        }
        orow[tid] = a;
    }
}

// ---------------------------------------------------------------------------
extern "C" void kernel_launch(void* const* d_in, const int* in_sizes, int n_in,
                              void* d_out, int out_size)
{
    const float* TE   = (const float*)d_in[0];   // (32,1024,1024) f32
    const float* Wt   = (const float*)d_in[1];   // (3072,1024) f32
    const float* bias = (const float*)d_in[2];   // (3072,) f32
    const int* idx    = (const int*)d_in[3];     // (32,128,6) i32
    float* out = (float*)d_out;

    // Kernel P: window scan + compact gather table + bias fp16
    scan_kernel<<<1, 1024>>>(idx, bias);

    // Kernel B': copy+zero AND TE->fp16 conversion (produces g_TEh)
    {
        size_t total4 = (size_t)Bn * Sn * Hn / 4;   // 8388608
        copy_zero_conv_kernel<<<(unsigned)(total4 / 256), 256>>>(TE, idx, out);
    }

    // Kernel W: W[0:2048] -> fp16 (produces g_Wh)
    {
        size_t total4 = (size_t)NCOLS * Hn / 4;     // 524288
        conv_w_kernel<<<(unsigned)(total4 / 256), 256>>>(Wt);
    }

    // Kernel A: compacted fp16 tensor-core projection GEMM into g_qkh
    {
        static bool attr_set = false;
        if (!attr_set) {
            cudaFuncSetAttribute(gemm_qk_f16,
                                 cudaFuncAttributeMaxDynamicSharedMemorySize,
                                 GEMM_SMEM);
            attr_set = true;
        }
        dim3 grid(NCOLS / 256, MROWS / 128);   // (8, 192); tail blocks exit
        gemm_qk_f16<<<grid, 512, GEMM_SMEM>>>(bias);
    }

    // Kernel C: attention + unified scatter (needs out + g_qkh + winStart)
    {
        static bool attr_set2 = false;
        if (!attr_set2) {
            cudaFuncSetAttribute(attn_merge_kernel,
                                 cudaFuncAttributeMaxDynamicSharedMemorySize,
                                 (int)sizeof(SmemB));
            attr_set2 = true;
        }
        attn_merge_kernel<<<NWIN, 256, sizeof(SmemB)>>>(TE, idx, out);
    }
}